// round 11
// baseline (speedup 1.0000x reference)
#include <cuda_runtime.h>
#include <cuda_bf16.h>
#include <cstdint>

// Problem constants
#define B_  32
#define S_  256
#define D_  17
#define M_  512
#define H_  8
#define DK_ 64
#define NROW  139264          // B*S*D rows of width 512
#define NSAMP 8192            // B*S

// ---------------------------------------------------------------------------
// Scratch (__device__ globals; allocation-free rule)
// ---------------------------------------------------------------------------
__device__ float g_q[(size_t)NROW * M_];
__device__ float g_k[(size_t)NROW * M_];
__device__ float g_v[(size_t)NROW * M_];
__device__ __nv_bfloat16 g_xh[(size_t)NROW * M_];
__device__ __nv_bfloat16 g_xl[(size_t)NROW * M_];
__device__ __nv_bfloat16 g_ch[(size_t)NROW * M_];
__device__ __nv_bfloat16 g_cl[(size_t)NROW * M_];
__device__ __nv_bfloat16 g_wh[4 * 512 * 512];   // Wq,Wk,Wv,Wo hi (rows contiguous)
__device__ __nv_bfloat16 g_wl[4 * 512 * 512];   // lo

// ---------------------------------------------------------------------------
// Helpers
// ---------------------------------------------------------------------------
__device__ __forceinline__ uint32_t smem_u32(const void* p) {
    uint32_t a;
    asm("{ .reg .u64 t; cvta.to.shared.u64 t, %1; cvt.u32.u64 %0, t; }"
        : "=r"(a) : "l"(p));
    return a;
}

__device__ __forceinline__ void cp16(uint32_t dst, const void* src) {
    asm volatile("cp.async.cg.shared.global [%0], [%1], 16;" :: "r"(dst), "l"(src));
}

__device__ __forceinline__ void ldmx4(uint32_t* r, uint32_t addr) {
    asm volatile("ldmatrix.sync.aligned.m8n8.x4.shared.b16 {%0,%1,%2,%3}, [%4];"
                 : "=r"(r[0]), "=r"(r[1]), "=r"(r[2]), "=r"(r[3]) : "r"(addr));
}

__device__ __forceinline__ void mma16816(float* d, const uint32_t* a,
                                         uint32_t b0, uint32_t b1) {
    asm volatile(
        "mma.sync.aligned.m16n8k16.row.col.f32.bf16.bf16.f32 "
        "{%0,%1,%2,%3}, {%4,%5,%6,%7}, {%8,%9}, {%0,%1,%2,%3};"
        : "+f"(d[0]), "+f"(d[1]), "+f"(d[2]), "+f"(d[3])
        : "r"(a[0]), "r"(a[1]), "r"(a[2]), "r"(a[3]), "r"(b0), "r"(b1));
}

// ---------------------------------------------------------------------------
// bf16-split GEMM on HMMA, fused-phase structure, 256-thread variant:
//   pass A (iters 0-7):  acc += xh.Wh + xh.Wl   (A LDSM shared by both B's)
//   pass B (iters 8-15): acc += xl.Wh
// BM=BN=128, BK=64/iter, 256 threads (8 warps 4m x 2n), warp tile 32x64.
// 2-stage double buffer (110.6KB) -> 2 CTAs/SM -> 4 warps per SMSP.
// ---------------------------------------------------------------------------
#define ITERS 16
#define ROWB 144
#define STAGE_BYTES (384 * ROWB)    // A(128) + B0(128) + B1(128) rows

__device__ __forceinline__ void load_iter(
    int tid, uint32_t sbase, int r0, int c0, int it,
    const __nv_bfloat16* __restrict__ xh, const __nv_bfloat16* __restrict__ xl,
    const __nv_bfloat16* __restrict__ Wh, const __nv_bfloat16* __restrict__ Wl)
{
    const int kk = (it & 7) * 64;
    const __nv_bfloat16* A = (it < 8) ? xh : xl;
    #pragma unroll
    for (int t = 0; t < 4; t++) {                 // A: 128 rows x 128B
        int f = tid + t * 256;
        int row = f >> 3, ch = f & 7;
        cp16(sbase + row * ROWB + ch * 16, A + ((size_t)(r0 + row) << 9) + kk + ch * 8);
    }
    const uint32_t b0 = sbase + 128 * ROWB;
    #pragma unroll
    for (int t = 0; t < 4; t++) {                 // B0 = Wh
        int f = tid + t * 256;
        int row = f >> 3, ch = f & 7;
        cp16(b0 + row * ROWB + ch * 16, Wh + ((size_t)(c0 + row) << 9) + kk + ch * 8);
    }
    if (it < 8) {
        const uint32_t b1 = sbase + 256 * ROWB;
        #pragma unroll
        for (int t = 0; t < 4; t++) {             // B1 = Wl (pass A only)
            int f = tid + t * 256;
            int row = f >> 3, ch = f & 7;
            cp16(b1 + row * ROWB + ch * 16, Wl + ((size_t)(c0 + row) << 9) + kk + ch * 8);
        }
    }
    asm volatile("cp.async.commit_group;");
}

template<int MODE>
__global__ __launch_bounds__(256)
void gemm_mma(const __nv_bfloat16* __restrict__ Ah,
              const __nv_bfloat16* __restrict__ Al,
              const __nv_bfloat16* __restrict__ Wh,
              const __nv_bfloat16* __restrict__ Wl,
              float* __restrict__ C0, float* __restrict__ C1,
              float* __restrict__ C2,
              const float* __restrict__ bias,
              const float* __restrict__ resid)
{
    extern __shared__ __align__(128) char smem[];

    const int tid = threadIdx.x;
    const int wid = tid >> 5;
    const int lid = tid & 31;
    const int c0 = blockIdx.x << 7;    // col tile (fast dim -> A L2 reuse)
    const int r0 = blockIdx.y << 7;
    const int m0 = (wid & 3) * 32;     // 4 warps in m
    const int n0 = (wid >> 2) * 64;    // 2 warps in n
    const uint32_t sb = smem_u32(smem);

    float acc[2][8][4];
    #pragma unroll
    for (int i = 0; i < 2; i++)
        #pragma unroll
        for (int j = 0; j < 8; j++)
            #pragma unroll
            for (int q = 0; q < 4; q++) acc[i][j][q] = 0.f;

    load_iter(tid, sb, r0, c0, 0, Ah, Al, Wh, Wl);

    const uint32_t a_off = (uint32_t)((m0 + (lid & 15)) * ROWB + ((lid >> 4) << 4));
    const uint32_t b_off = (uint32_t)((n0 + (lid & 7) + ((lid >> 4) << 3)) * ROWB
                                      + (((lid >> 3) & 1) << 4));

    for (int it = 0; it < ITERS; it++) {
        asm volatile("cp.async.wait_group 0;");
        __syncthreads();

        if (it + 1 < ITERS)
            load_iter(tid, sb + ((it + 1) & 1) * STAGE_BYTES, r0, c0, it + 1,
                      Ah, Al, Wh, Wl);

        const uint32_t as  = sb + (it & 1) * STAGE_BYTES;
        const uint32_t bs0 = as + 128 * ROWB;
        const uint32_t bs1 = as + 256 * ROWB;

        #pragma unroll
        for (int kt = 0; kt < 4; kt++) {
            uint32_t a[2][4], b[4][4];
            #pragma unroll
            for (int mi = 0; mi < 2; mi++)
                ldmx4(a[mi], as + a_off + (uint32_t)(mi * 16 * ROWB + kt * 32));
            #pragma unroll
            for (int nj = 0; nj < 4; nj++)
                ldmx4(b[nj], bs0 + b_off + (uint32_t)(nj * 16 * ROWB + kt * 32));
            #pragma unroll
            for (int mi = 0; mi < 2; mi++)
                #pragma unroll
                for (int ni = 0; ni < 8; ni++)
                    mma16816(acc[mi][ni], a[mi],
                             b[ni >> 1][(ni & 1) * 2], b[ni >> 1][(ni & 1) * 2 + 1]);
            if (it < 8) {   // pass A: second B tile (Wl), reuse A fragments
                #pragma unroll
                for (int nj = 0; nj < 4; nj++)
                    ldmx4(b[nj], bs1 + b_off + (uint32_t)(nj * 16 * ROWB + kt * 32));
                #pragma unroll
                for (int mi = 0; mi < 2; mi++)
                    #pragma unroll
                    for (int ni = 0; ni < 8; ni++)
                        mma16816(acc[mi][ni], a[mi],
                                 b[ni >> 1][(ni & 1) * 2], b[ni >> 1][(ni & 1) * 2 + 1]);
            }
        }
    }

    // Epilogue
    float* C;
    int col0;
    if (MODE == 0) {
        const int which = c0 >> 9;
        C = (which == 0) ? C0 : (which == 1) ? C1 : C2;
        col0 = c0 & 511;
    } else {
        C = C0;
        col0 = c0;
    }
    const int g  = lid >> 2;
    const int tg = lid & 3;
    #pragma unroll
    for (int mi = 0; mi < 2; mi++) {
        #pragma unroll
        for (int ni = 0; ni < 8; ni++) {
            const int r = r0 + m0 + mi * 16 + g;
            const int c = col0 + n0 + ni * 8 + tg * 2;
            float2 v0 = make_float2(acc[mi][ni][0], acc[mi][ni][1]);
            float2 v1 = make_float2(acc[mi][ni][2], acc[mi][ni][3]);
            if (MODE == 1) {
                const float2 bb = *(const float2*)(bias + c);
                const float2 q0 = *(const float2*)(resid + ((size_t)r << 9) + c);
                const float2 q1 = *(const float2*)(resid + ((size_t)(r + 8) << 9) + c);
                v0.x += bb.x + q0.x; v0.y += bb.y + q0.y;
                v1.x += bb.x + q1.x; v1.y += bb.y + q1.y;
            }
            *(float2*)(C + ((size_t)r << 9) + c)       = v0;
            *(float2*)(C + ((size_t)(r + 8) << 9) + c) = v1;
        }
    }
}

// ---------------------------------------------------------------------------
// fp32 -> (bf16 hi, bf16 lo) splits
// ---------------------------------------------------------------------------
__global__ __launch_bounds__(256)
void wsplit_kernel(const float* __restrict__ Wq, const float* __restrict__ Wk,
                   const float* __restrict__ Wv, const float* __restrict__ Wo,
                   __nv_bfloat16* __restrict__ hi, __nv_bfloat16* __restrict__ lo)
{
    const int w = blockIdx.y;
    const float* src = (w == 0) ? Wq : (w == 1) ? Wk : (w == 2) ? Wv : Wo;
    const int i = blockIdx.x * 256 + threadIdx.x;      // < 65536
    float4 v = ((const float4*)src)[i];
    __nv_bfloat16 h0 = __float2bfloat16(v.x);
    __nv_bfloat16 h1 = __float2bfloat16(v.y);
    __nv_bfloat16 h2 = __float2bfloat16(v.z);
    __nv_bfloat16 h3 = __float2bfloat16(v.w);
    __nv_bfloat162* hp = (__nv_bfloat162*)(hi + (size_t)w * 262144);
    __nv_bfloat162* lp = (__nv_bfloat162*)(lo + (size_t)w * 262144);
    hp[2 * i]     = __nv_bfloat162(h0, h1);
    hp[2 * i + 1] = __nv_bfloat162(h2, h3);
    lp[2 * i]     = __nv_bfloat162(__float2bfloat16(v.x - __bfloat162float(h0)),
                                   __float2bfloat16(v.y - __bfloat162float(h1)));
    lp[2 * i + 1] = __nv_bfloat162(__float2bfloat16(v.z - __bfloat162float(h2)),
                                   __float2bfloat16(v.w - __bfloat162float(h3)));
}

__global__ __launch_bounds__(256)
void split_kernel(const float* __restrict__ in, __nv_bfloat16* __restrict__ hi,
                  __nv_bfloat16* __restrict__ lo, int n4)
{
    int i = blockIdx.x * 256 + threadIdx.x;
    if (i >= n4) return;
    float4 v = ((const float4*)in)[i];
    __nv_bfloat16 h0 = __float2bfloat16(v.x);
    __nv_bfloat16 h1 = __float2bfloat16(v.y);
    __nv_bfloat16 h2 = __float2bfloat16(v.z);
    __nv_bfloat16 h3 = __float2bfloat16(v.w);
    __nv_bfloat162* hp = (__nv_bfloat162*)hi;
    __nv_bfloat162* lp = (__nv_bfloat162*)lo;
    hp[2 * i]     = __nv_bfloat162(h0, h1);
    hp[2 * i + 1] = __nv_bfloat162(h2, h3);
    lp[2 * i]     = __nv_bfloat162(__float2bfloat16(v.x - __bfloat162float(h0)),
                                   __float2bfloat16(v.y - __bfloat162float(h1)));
    lp[2 * i + 1] = __nv_bfloat162(__float2bfloat16(v.z - __bfloat162float(h2)),
                                   __float2bfloat16(v.w - __bfloat162float(h3)));
}

// ---------------------------------------------------------------------------
// Attention v5 (R10 best, unchanged): buffer-reuse staging, padded score
// writes. smem = 11248 floats = 45.0KB -> 5 CTAs/SM.
// ---------------------------------------------------------------------------
#define AB0 0
#define AB1 4624
#define ASS 9248                 // 4 heads * 400
#define ASP 10848                // 400
__global__ __launch_bounds__(128)
void attn_kernel(const float* __restrict__ q, const float* __restrict__ k,
                 const float* __restrict__ v, const float* __restrict__ P,
                 __nv_bfloat16* __restrict__ ch, __nv_bfloat16* __restrict__ cl)
{
    __shared__ float sm[11248];  // 44992 bytes
    const int n  = blockIdx.x;
    const int hg = blockIdx.y;
    const int t  = threadIdx.x;
    const size_t base = (size_t)n * D_ * M_;

    // Phase 1: stage q -> BUF0, k -> BUF1 ([h][d][c], row stride 68)
    for (int f = t; f < 1088; f += 128) {
        int d = f >> 6, hc = f & 63;
        int h = hc >> 4, c4 = hc & 15;
        size_t goff = base + (size_t)d * 512 + (hg * 4 + h) * 64 + c4 * 4;
        int soff = (h * 17 + d) * 68 + c4 * 4;
        *(float4*)(sm + AB0 + soff) = *(const float4*)(q + goff);
        *(float4*)(sm + AB1 + soff) = *(const float4*)(k + goff);
    }
    for (int f = t; f < 289; f += 128)
        sm[ASP + (f / 17) * 20 + (f % 17)] = P[f];
    __syncthreads();

    // Phase 2: scores, 4 heads x 25 blocks of 4x4 = 100 tasks (padded blocks)
    if (t < 100) {
        const int h = t / 25, blk = t % 25;
        const int d0 = (blk / 5) * 4, e0 = (blk % 5) * 4;
        const float* sq = sm + AB0 + (h * 17 + d0) * 68;
        const float* sk = sm + AB1 + (h * 17 + e0) * 68;
        float acc[4][4];
        #pragma unroll
        for (int i = 0; i < 4; i++)
            #pragma unroll
            for (int j = 0; j < 4; j++) acc[i][j] = 0.f;
        #pragma unroll 4
        for (int c4 = 0; c4 < 16; c4++) {
            float4 qa[4], kb[4];
            #pragma unroll
            for (int i = 0; i < 4; i++) qa[i] = *(const float4*)(sq + i * 68 + c4 * 4);
            #pragma unroll
            for (int j = 0; j < 4; j++) kb[j] = *(const float4*)(sk + j * 68 + c4 * 4);
            #pragma unroll
            for (int i = 0; i < 4; i++)
                #pragma unroll
                for (int j = 0; j < 4; j++)
                    acc[i][j] += qa[i].x * kb[j].x + qa[i].y * kb[j].y
                               + qa[i].z * kb[j].z + qa[i].w * kb[j].w;
        }
        float* ss = sm + ASS + h * 400;
        #pragma unroll
        for (int i = 0; i < 4; i++)
            #pragma unroll
            for (int j = 0; j < 4; j++)
                ss[(d0 + i) * 20 + e0 + j] =
                    acc[i][j] * 0.125f + sm[ASP + (d0 + i) * 20 + e0 + j];
    }
    __syncthreads();

    // Phase 3: stage v into BUF0 (q no longer needed) + softmax on ss
    for (int f = t; f < 1088; f += 128) {
        int d = f >> 6, hc = f & 63;
        int h = hc >> 4, c4 = hc & 15;
        size_t goff = base + (size_t)d * 512 + (hg * 4 + h) * 64 + c4 * 4;
        *(float4*)(sm + AB0 + (h * 17 + d) * 68 + c4 * 4) = *(const float4*)(v + goff);
    }
    if (t < 68) {
        float* row = sm + ASS + (t / 17) * 400 + (t % 17) * 20;
        float mx = -1e30f;
        #pragma unroll
        for (int e = 0; e < 17; e++) mx = fmaxf(mx, row[e]);
        float sum = 0.f;
        #pragma unroll
        for (int e = 0; e < 17; e++) {
            float ex = __expf(row[e] - mx);
            row[e] = ex;
            sum += ex;
        }
        float inv = 1.f / sum;
        #pragma unroll
        for (int e = 0; e < 17; e++) row[e] *= inv;
    }
    __syncthreads();

    // Phase 4: ctx, 4 heads x (5 dblk x 16 cblk) = 320 tasks -> bf16 hi/lo
    for (int task = t; task < 320; task += 128) {
        const int h = task / 80, rem = task % 80;
        const int d0 = (rem / 16) * 4, c0c = (rem % 16) * 4;
        const float* ss = sm + ASS + h * 400;
        const float* sv = sm + AB0 + h * 17 * 68 + c0c;
        float acc[4][4];
        #pragma unroll
        for (int i = 0; i < 4; i++)
            #pragma unroll
            for (int j = 0; j < 4; j++) acc[i][j] = 0.f;
        #pragma unroll 1
        for (int e = 0; e < 17; e++) {
            const float4 vv = *(const float4*)(sv + e * 68);
            #pragma unroll
            for (int i = 0; i < 4; i++) {
                const float w = ss[(d0 + i) * 20 + e];
                acc[i][0] += w * vv.x;
                acc[i][1] += w * vv.y;
                acc[i][2] += w * vv.z;
                acc[i][3] += w * vv.w;
            }
        }
        #pragma unroll
        for (int i = 0; i < 4; i++) {
            const int d = d0 + i;
            if (d < 17) {
                const size_t off = base + (size_t)d * 512 + (hg * 4 + h) * 64 + c0c;
                __nv_bfloat16 hh[4], ll[4];
                #pragma unroll
                for (int j = 0; j < 4; j++) {
                    hh[j] = __float2bfloat16(acc[i][j]);
                    ll[j] = __float2bfloat16(acc[i][j] - __bfloat162float(hh[j]));
                }
                *(uint2*)(ch + off) = *(uint2*)hh;
                *(uint2*)(cl + off) = *(uint2*)ll;
            }
        }
    }
}

// ---------------------------------------------------------------------------
// In-place LayerNorm (warp per row, width 512), eps = 1e-5
// ---------------------------------------------------------------------------
__global__ __launch_bounds__(256)
void ln_kernel(float* __restrict__ out, const float* __restrict__ gamma,
               const float* __restrict__ beta)
{
    const int row  = blockIdx.x * 8 + (threadIdx.x >> 5);
    const int lane = threadIdx.x & 31;
    const size_t base = (size_t)row * 512;

    float4 vals[4];
    float sum = 0.f, sq = 0.f;
    #pragma unroll
    for (int j = 0; j < 4; j++) {
        vals[j] = *(const float4*)(out + base + (size_t)(j * 32 + lane) * 4);
        sum += vals[j].x + vals[j].y + vals[j].z + vals[j].w;
        sq  += vals[j].x * vals[j].x + vals[j].y * vals[j].y
             + vals[j].z * vals[j].z + vals[j].w * vals[j].w;
    }
    #pragma unroll
    for (int o = 16; o > 0; o >>= 1) {
        sum += __shfl_xor_sync(0xffffffffu, sum, o);
        sq  += __shfl_xor_sync(0xffffffffu, sq,  o);
    }
    const float mean = sum * (1.f / 512.f);
    const float var  = sq * (1.f / 512.f) - mean * mean;
    const float rstd = rsqrtf(var + 1e-5f);

    #pragma unroll
    for (int j = 0; j < 4; j++) {
        int c = (j * 32 + lane) * 4;
        float4 g  = *(const float4*)(gamma + c);
        float4 bb = *(const float4*)(beta + c);
        float4 v;
        v.x = (vals[j].x - mean) * rstd * g.x + bb.x;
        v.y = (vals[j].y - mean) * rstd * g.y + bb.y;
        v.z = (vals[j].z - mean) * rstd * g.z + bb.z;
        v.w = (vals[j].w - mean) * rstd * g.w + bb.w;
        *(float4*)(out + base + c) = v;
    }
}

// ---------------------------------------------------------------------------
extern "C" void kernel_launch(void* const* d_in, const int* in_sizes, int n_in,
                              void* d_out, int out_size)
{
    const float* x     = (const float*)d_in[0];
    const float* P     = (const float*)d_in[1];
    const float* Wq    = (const float*)d_in[2];
    const float* Wk    = (const float*)d_in[3];
    const float* Wv    = (const float*)d_in[4];
    const float* Wo    = (const float*)d_in[5];
    const float* bo    = (const float*)d_in[6];
    const float* gamma = (const float*)d_in[7];
    const float* beta  = (const float*)d_in[8];
    float* out = (float*)d_out;

    void *pq, *pk, *pv, *pxh, *pxl, *pch, *pcl, *pwh, *pwl;
    cudaGetSymbolAddress(&pq,  g_q);
    cudaGetSymbolAddress(&pk,  g_k);
    cudaGetSymbolAddress(&pv,  g_v);
    cudaGetSymbolAddress(&pxh, g_xh);
    cudaGetSymbolAddress(&pxl, g_xl);
    cudaGetSymbolAddress(&pch, g_ch);
    cudaGetSymbolAddress(&pcl, g_cl);
    cudaGetSymbolAddress(&pwh, g_wh);
    cudaGetSymbolAddress(&pwl, g_wl);

    __nv_bfloat16* wh = (__nv_bfloat16*)pwh;
    __nv_bfloat16* wl = (__nv_bfloat16*)pwl;

    const int dsm = 2 * STAGE_BYTES;                // 110592
    cudaFuncSetAttribute(gemm_mma<0>, cudaFuncAttributeMaxDynamicSharedMemorySize, dsm);
    cudaFuncSetAttribute(gemm_mma<1>, cudaFuncAttributeMaxDynamicSharedMemorySize, dsm);

    // Splits
    dim3 gw(256, 4);
    wsplit_kernel<<<gw, 256>>>(Wq, Wk, Wv, Wo, wh, wl);
    const int nx4 = (int)((size_t)NROW * 512 / 4);
    split_kernel<<<(nx4 + 255) / 256, 256>>>(x, (__nv_bfloat16*)pxh,
                                             (__nv_bfloat16*)pxl, nx4);

    // Fused QKV projection: 12 col tiles over contiguous [Wq;Wk;Wv] rows
    dim3 gq(12, NROW / 128);
    gemm_mma<0><<<gq, 256, dsm>>>((const __nv_bfloat16*)pxh, (const __nv_bfloat16*)pxl,
                                  wh, wl,
                                  (float*)pq, (float*)pk, (float*)pv,
                                  nullptr, nullptr);

    dim3 ga(NSAMP, 2);
    attn_kernel<<<ga, 128>>>(
        (const float*)pq, (const float*)pk, (const float*)pv, P,
        (__nv_bfloat16*)pch, (__nv_bfloat16*)pcl);

    // fc_out + bias + residual
    dim3 go(4, NROW / 128);
    gemm_mma<1><<<go, 256, dsm>>>((const __nv_bfloat16*)pch, (const __nv_bfloat16*)pcl,
                                  wh + 3 * 262144, wl + 3 * 262144,
                                  out, nullptr, nullptr, bo, x);

    ln_kernel<<<NROW / 8, 256>>>(out, gamma, beta);
}

// round 12
// speedup vs baseline: 1.0509x; 1.0509x over previous
#include <cuda_runtime.h>
#include <cuda_bf16.h>
#include <cstdint>

// Problem constants
#define B_  32
#define S_  256
#define D_  17
#define M_  512
#define H_  8
#define DK_ 64
#define NROW  139264          // B*S*D rows of width 512
#define NSAMP 8192            // B*S

// ---------------------------------------------------------------------------
// Scratch (__device__ globals; allocation-free rule)
// ---------------------------------------------------------------------------
__device__ float g_q[(size_t)NROW * M_];
__device__ float g_k[(size_t)NROW * M_];
__device__ float g_v[(size_t)NROW * M_];
__device__ __nv_bfloat16 g_xh[(size_t)NROW * M_];
__device__ __nv_bfloat16 g_xl[(size_t)NROW * M_];
__device__ __nv_bfloat16 g_ch[(size_t)NROW * M_];
__device__ __nv_bfloat16 g_cl[(size_t)NROW * M_];
__device__ __nv_bfloat16 g_wh[4 * 512 * 512];   // Wq,Wk,Wv,Wo hi (rows contiguous)
__device__ __nv_bfloat16 g_wl[4 * 512 * 512];   // lo

// ---------------------------------------------------------------------------
// Helpers
// ---------------------------------------------------------------------------
__device__ __forceinline__ uint32_t smem_u32(const void* p) {
    uint32_t a;
    asm("{ .reg .u64 t; cvta.to.shared.u64 t, %1; cvt.u32.u64 %0, t; }"
        : "=r"(a) : "l"(p));
    return a;
}

__device__ __forceinline__ void cp16(uint32_t dst, const void* src) {
    asm volatile("cp.async.cg.shared.global [%0], [%1], 16;" :: "r"(dst), "l"(src));
}

__device__ __forceinline__ void ldmx4(uint32_t* r, uint32_t addr) {
    asm volatile("ldmatrix.sync.aligned.m8n8.x4.shared.b16 {%0,%1,%2,%3}, [%4];"
                 : "=r"(r[0]), "=r"(r[1]), "=r"(r[2]), "=r"(r[3]) : "r"(addr));
}

__device__ __forceinline__ void mma16816(float* d, const uint32_t* a,
                                         uint32_t b0, uint32_t b1) {
    asm volatile(
        "mma.sync.aligned.m16n8k16.row.col.f32.bf16.bf16.f32 "
        "{%0,%1,%2,%3}, {%4,%5,%6,%7}, {%8,%9}, {%0,%1,%2,%3};"
        : "+f"(d[0]), "+f"(d[1]), "+f"(d[2]), "+f"(d[3])
        : "r"(a[0]), "r"(a[1]), "r"(a[2]), "r"(a[3]), "r"(b0), "r"(b1));
}

// ---------------------------------------------------------------------------
// bf16-split GEMM on HMMA, fused-phase structure (R10 best, exact revert):
//   pass A (iters 0-7):  acc += xh.Wh + xh.Wl   (A LDSM shared by both B's)
//   pass B (iters 8-15): acc += xl.Wh
// BM=BN=128, BK=64 per iter, 128 threads (4 warps 2x2), warp tile 64x64.
// ---------------------------------------------------------------------------
#define ITERS 16
#define ROWB 144
#define STAGE_BYTES (384 * ROWB)    // A(128) + B0(128) + B1(128) rows

__device__ __forceinline__ void load_iter(
    int tid, uint32_t sbase, int r0, int c0, int it,
    const __nv_bfloat16* __restrict__ xh, const __nv_bfloat16* __restrict__ xl,
    const __nv_bfloat16* __restrict__ Wh, const __nv_bfloat16* __restrict__ Wl)
{
    const int kk = (it & 7) * 64;
    const __nv_bfloat16* A = (it < 8) ? xh : xl;
    #pragma unroll
    for (int t = 0; t < 8; t++) {                 // A: 128 rows x 128B
        int f = tid + t * 128;
        int row = f >> 3, ch = f & 7;
        cp16(sbase + row * ROWB + ch * 16, A + ((size_t)(r0 + row) << 9) + kk + ch * 8);
    }
    const uint32_t b0 = sbase + 128 * ROWB;
    #pragma unroll
    for (int t = 0; t < 8; t++) {                 // B0 = Wh
        int f = tid + t * 128;
        int row = f >> 3, ch = f & 7;
        cp16(b0 + row * ROWB + ch * 16, Wh + ((size_t)(c0 + row) << 9) + kk + ch * 8);
    }
    if (it < 8) {
        const uint32_t b1 = sbase + 256 * ROWB;
        #pragma unroll
        for (int t = 0; t < 8; t++) {             // B1 = Wl (pass A only)
            int f = tid + t * 128;
            int row = f >> 3, ch = f & 7;
            cp16(b1 + row * ROWB + ch * 16, Wl + ((size_t)(c0 + row) << 9) + kk + ch * 8);
        }
    }
    asm volatile("cp.async.commit_group;");
}

template<int MODE>
__global__ __launch_bounds__(128)
void gemm_mma(const __nv_bfloat16* __restrict__ Ah,
              const __nv_bfloat16* __restrict__ Al,
              const __nv_bfloat16* __restrict__ Wh,
              const __nv_bfloat16* __restrict__ Wl,
              float* __restrict__ C0, float* __restrict__ C1,
              float* __restrict__ C2,
              const float* __restrict__ bias,
              const float* __restrict__ resid)
{
    extern __shared__ __align__(128) char smem[];

    const int tid = threadIdx.x;
    const int wid = tid >> 5;
    const int lid = tid & 31;
    const int c0 = blockIdx.x << 7;    // col tile (fast dim -> A L2 reuse)
    const int r0 = blockIdx.y << 7;
    const int m0 = (wid & 1) * 64;
    const int n0 = (wid >> 1) * 64;
    const uint32_t sb = smem_u32(smem);

    float acc[4][8][4];
    #pragma unroll
    for (int i = 0; i < 4; i++)
        #pragma unroll
        for (int j = 0; j < 8; j++)
            #pragma unroll
            for (int q = 0; q < 4; q++) acc[i][j][q] = 0.f;

    load_iter(tid, sb, r0, c0, 0, Ah, Al, Wh, Wl);

    const uint32_t a_off = (uint32_t)((m0 + (lid & 15)) * ROWB + ((lid >> 4) << 4));
    const uint32_t b_off = (uint32_t)((n0 + (lid & 7) + ((lid >> 4) << 3)) * ROWB
                                      + (((lid >> 3) & 1) << 4));

    for (int it = 0; it < ITERS; it++) {
        asm volatile("cp.async.wait_group 0;");
        __syncthreads();

        if (it + 1 < ITERS)
            load_iter(tid, sb + ((it + 1) & 1) * STAGE_BYTES, r0, c0, it + 1,
                      Ah, Al, Wh, Wl);

        const uint32_t as  = sb + (it & 1) * STAGE_BYTES;
        const uint32_t bs0 = as + 128 * ROWB;
        const uint32_t bs1 = as + 256 * ROWB;

        #pragma unroll
        for (int kt = 0; kt < 4; kt++) {
            uint32_t a[4][4], b[4][4];
            #pragma unroll
            for (int mi = 0; mi < 4; mi++)
                ldmx4(a[mi], as + a_off + (uint32_t)(mi * 16 * ROWB + kt * 32));
            #pragma unroll
            for (int nj = 0; nj < 4; nj++)
                ldmx4(b[nj], bs0 + b_off + (uint32_t)(nj * 16 * ROWB + kt * 32));
            #pragma unroll
            for (int mi = 0; mi < 4; mi++)
                #pragma unroll
                for (int ni = 0; ni < 8; ni++)
                    mma16816(acc[mi][ni], a[mi],
                             b[ni >> 1][(ni & 1) * 2], b[ni >> 1][(ni & 1) * 2 + 1]);
            if (it < 8) {   // pass A: second B tile (Wl), reuse A fragments
                #pragma unroll
                for (int nj = 0; nj < 4; nj++)
                    ldmx4(b[nj], bs1 + b_off + (uint32_t)(nj * 16 * ROWB + kt * 32));
                #pragma unroll
                for (int mi = 0; mi < 4; mi++)
                    #pragma unroll
                    for (int ni = 0; ni < 8; ni++)
                        mma16816(acc[mi][ni], a[mi],
                                 b[ni >> 1][(ni & 1) * 2], b[ni >> 1][(ni & 1) * 2 + 1]);
            }
        }
    }

    // Epilogue
    float* C;
    int col0;
    if (MODE == 0) {
        const int which = c0 >> 9;
        C = (which == 0) ? C0 : (which == 1) ? C1 : C2;
        col0 = c0 & 511;
    } else {
        C = C0;
        col0 = c0;
    }
    const int g  = lid >> 2;
    const int tg = lid & 3;
    #pragma unroll
    for (int mi = 0; mi < 4; mi++) {
        #pragma unroll
        for (int ni = 0; ni < 8; ni++) {
            const int r = r0 + m0 + mi * 16 + g;
            const int c = col0 + n0 + ni * 8 + tg * 2;
            float2 v0 = make_float2(acc[mi][ni][0], acc[mi][ni][1]);
            float2 v1 = make_float2(acc[mi][ni][2], acc[mi][ni][3]);
            if (MODE == 1) {
                const float2 bb = *(const float2*)(bias + c);
                const float2 q0 = *(const float2*)(resid + ((size_t)r << 9) + c);
                const float2 q1 = *(const float2*)(resid + ((size_t)(r + 8) << 9) + c);
                v0.x += bb.x + q0.x; v0.y += bb.y + q0.y;
                v1.x += bb.x + q1.x; v1.y += bb.y + q1.y;
            }
            *(float2*)(C + ((size_t)r << 9) + c)       = v0;
            *(float2*)(C + ((size_t)(r + 8) << 9) + c) = v1;
        }
    }
}

// ---------------------------------------------------------------------------
// fp32 -> (bf16 hi, bf16 lo) splits
// ---------------------------------------------------------------------------
__global__ __launch_bounds__(256)
void wsplit_kernel(const float* __restrict__ Wq, const float* __restrict__ Wk,
                   const float* __restrict__ Wv, const float* __restrict__ Wo,
                   __nv_bfloat16* __restrict__ hi, __nv_bfloat16* __restrict__ lo)
{
    const int w = blockIdx.y;
    const float* src = (w == 0) ? Wq : (w == 1) ? Wk : (w == 2) ? Wv : Wo;
    const int i = blockIdx.x * 256 + threadIdx.x;      // < 65536
    float4 v = ((const float4*)src)[i];
    __nv_bfloat16 h0 = __float2bfloat16(v.x);
    __nv_bfloat16 h1 = __float2bfloat16(v.y);
    __nv_bfloat16 h2 = __float2bfloat16(v.z);
    __nv_bfloat16 h3 = __float2bfloat16(v.w);
    __nv_bfloat162* hp = (__nv_bfloat162*)(hi + (size_t)w * 262144);
    __nv_bfloat162* lp = (__nv_bfloat162*)(lo + (size_t)w * 262144);
    hp[2 * i]     = __nv_bfloat162(h0, h1);
    hp[2 * i + 1] = __nv_bfloat162(h2, h3);
    lp[2 * i]     = __nv_bfloat162(__float2bfloat16(v.x - __bfloat162float(h0)),
                                   __float2bfloat16(v.y - __bfloat162float(h1)));
    lp[2 * i + 1] = __nv_bfloat162(__float2bfloat16(v.z - __bfloat162float(h2)),
                                   __float2bfloat16(v.w - __bfloat162float(h3)));
}

__global__ __launch_bounds__(256)
void split_kernel(const float* __restrict__ in, __nv_bfloat16* __restrict__ hi,
                  __nv_bfloat16* __restrict__ lo, int n4)
{
    int i = blockIdx.x * 256 + threadIdx.x;
    if (i >= n4) return;
    float4 v = ((const float4*)in)[i];
    __nv_bfloat16 h0 = __float2bfloat16(v.x);
    __nv_bfloat16 h1 = __float2bfloat16(v.y);
    __nv_bfloat16 h2 = __float2bfloat16(v.z);
    __nv_bfloat16 h3 = __float2bfloat16(v.w);
    __nv_bfloat162* hp = (__nv_bfloat162*)hi;
    __nv_bfloat162* lp = (__nv_bfloat162*)lo;
    hp[2 * i]     = __nv_bfloat162(h0, h1);
    hp[2 * i + 1] = __nv_bfloat162(h2, h3);
    lp[2 * i]     = __nv_bfloat162(__float2bfloat16(v.x - __bfloat162float(h0)),
                                   __float2bfloat16(v.y - __bfloat162float(h1)));
    lp[2 * i + 1] = __nv_bfloat162(__float2bfloat16(v.z - __bfloat162float(h2)),
                                   __float2bfloat16(v.w - __bfloat162float(h3)));
}

// ---------------------------------------------------------------------------
// Attention v6: R10 layout (buffer reuse, padded scores, 45KB, 5 CTAs/SM)
// + cp.async staging for q/k (phase 1) and v (phase 3, overlaps softmax)
// + fuller unrolls in score/ctx loops for ILP.
// ---------------------------------------------------------------------------
#define AB0 0
#define AB1 4624
#define ASS 9248                 // 4 heads * 400
#define ASP 10848                // 400
__global__ __launch_bounds__(128)
void attn_kernel(const float* __restrict__ q, const float* __restrict__ k,
                 const float* __restrict__ v, const float* __restrict__ P,
                 __nv_bfloat16* __restrict__ ch, __nv_bfloat16* __restrict__ cl)
{
    __shared__ float sm[11248];  // 44992 bytes
    const int n  = blockIdx.x;
    const int hg = blockIdx.y;
    const int t  = threadIdx.x;
    const size_t base = (size_t)n * D_ * M_;
    const uint32_t smb = smem_u32(sm);

    // Phase 1: cp.async stage q -> BUF0, k -> BUF1 ([h][d][c], stride 68);
    // P loads (LDG) overlap with the async staging.
    #pragma unroll
    for (int u = 0; u < 9; u++) {
        int f = t + u * 128;
        if (f < 1088) {
            int d = f >> 6, hc = f & 63;
            int h = hc >> 4, c4 = hc & 15;
            size_t goff = base + (size_t)d * 512 + (hg * 4 + h) * 64 + c4 * 4;
            uint32_t soff = (uint32_t)(((h * 17 + d) * 68 + c4 * 4) * 4);
            cp16(smb + AB0 * 4 + soff, q + goff);
            cp16(smb + AB1 * 4 + soff, k + goff);
        }
    }
    asm volatile("cp.async.commit_group;");
    for (int f = t; f < 289; f += 128)
        sm[ASP + (f / 17) * 20 + (f % 17)] = P[f];
    asm volatile("cp.async.wait_group 0;");
    __syncthreads();

    // Phase 2: scores, 4 heads x 25 blocks of 4x4 = 100 tasks (padded blocks)
    if (t < 100) {
        const int h = t / 25, blk = t % 25;
        const int d0 = (blk / 5) * 4, e0 = (blk % 5) * 4;
        const float* sq = sm + AB0 + (h * 17 + d0) * 68;
        const float* sk = sm + AB1 + (h * 17 + e0) * 68;
        float acc[4][4];
        #pragma unroll
        for (int i = 0; i < 4; i++)
            #pragma unroll
            for (int j = 0; j < 4; j++) acc[i][j] = 0.f;
        #pragma unroll 8
        for (int c4 = 0; c4 < 16; c4++) {
            float4 qa[4], kb[4];
            #pragma unroll
            for (int i = 0; i < 4; i++) qa[i] = *(const float4*)(sq + i * 68 + c4 * 4);
            #pragma unroll
            for (int j = 0; j < 4; j++) kb[j] = *(const float4*)(sk + j * 68 + c4 * 4);
            #pragma unroll
            for (int i = 0; i < 4; i++)
                #pragma unroll
                for (int j = 0; j < 4; j++)
                    acc[i][j] += qa[i].x * kb[j].x + qa[i].y * kb[j].y
                               + qa[i].z * kb[j].z + qa[i].w * kb[j].w;
        }
        float* ss = sm + ASS + h * 400;
        #pragma unroll
        for (int i = 0; i < 4; i++)
            #pragma unroll
            for (int j = 0; j < 4; j++)
                ss[(d0 + i) * 20 + e0 + j] =
                    acc[i][j] * 0.125f + sm[ASP + (d0 + i) * 20 + e0 + j];
    }
    __syncthreads();

    // Phase 3: cp.async v into BUF0 (q dead); softmax overlaps the copy.
    #pragma unroll
    for (int u = 0; u < 9; u++) {
        int f = t + u * 128;
        if (f < 1088) {
            int d = f >> 6, hc = f & 63;
            int h = hc >> 4, c4 = hc & 15;
            size_t goff = base + (size_t)d * 512 + (hg * 4 + h) * 64 + c4 * 4;
            uint32_t soff = (uint32_t)(((h * 17 + d) * 68 + c4 * 4) * 4);
            cp16(smb + AB0 * 4 + soff, v + goff);
        }
    }
    asm volatile("cp.async.commit_group;");
    if (t < 68) {
        float* row = sm + ASS + (t / 17) * 400 + (t % 17) * 20;
        float mx = -1e30f;
        #pragma unroll
        for (int e = 0; e < 17; e++) mx = fmaxf(mx, row[e]);
        float sum = 0.f;
        #pragma unroll
        for (int e = 0; e < 17; e++) {
            float ex = __expf(row[e] - mx);
            row[e] = ex;
            sum += ex;
        }
        float inv = 1.f / sum;
        #pragma unroll
        for (int e = 0; e < 17; e++) row[e] *= inv;
    }
    asm volatile("cp.async.wait_group 0;");
    __syncthreads();

    // Phase 4: ctx, 4 heads x (5 dblk x 16 cblk) = 320 tasks -> bf16 hi/lo
    for (int task = t; task < 320; task += 128) {
        const int h = task / 80, rem = task % 80;
        const int d0 = (rem / 16) * 4, c0c = (rem % 16) * 4;
        const float* ss = sm + ASS + h * 400;
        const float* sv = sm + AB0 + h * 17 * 68 + c0c;
        float acc[4][4];
        #pragma unroll
        for (int i = 0; i < 4; i++)
            #pragma unroll
            for (int j = 0; j < 4; j++) acc[i][j] = 0.f;
        #pragma unroll
        for (int e = 0; e < 17; e++) {
            const float4 vv = *(const float4*)(sv + e * 68);
            #pragma unroll
            for (int i = 0; i < 4; i++) {
                const float w = ss[(d0 + i) * 20 + e];
                acc[i][0] += w * vv.x;
                acc[i][1] += w * vv.y;
                acc[i][2] += w * vv.z;
                acc[i][3] += w * vv.w;
            }
        }
        #pragma unroll
        for (int i = 0; i < 4; i++) {
            const int d = d0 + i;
            if (d < 17) {
                const size_t off = base + (size_t)d * 512 + (hg * 4 + h) * 64 + c0c;
                __nv_bfloat16 hh[4], ll[4];
                #pragma unroll
                for (int j = 0; j < 4; j++) {
                    hh[j] = __float2bfloat16(acc[i][j]);
                    ll[j] = __float2bfloat16(acc[i][j] - __bfloat162float(hh[j]));
                }
                *(uint2*)(ch + off) = *(uint2*)hh;
                *(uint2*)(cl + off) = *(uint2*)ll;
            }
        }
    }
}

// ---------------------------------------------------------------------------
// In-place LayerNorm (warp per row, width 512), eps = 1e-5
// ---------------------------------------------------------------------------
__global__ __launch_bounds__(256)
void ln_kernel(float* __restrict__ out, const float* __restrict__ gamma,
               const float* __restrict__ beta)
{
    const int row  = blockIdx.x * 8 + (threadIdx.x >> 5);
    const int lane = threadIdx.x & 31;
    const size_t base = (size_t)row * 512;

    float4 vals[4];
    float sum = 0.f, sq = 0.f;
    #pragma unroll
    for (int j = 0; j < 4; j++) {
        vals[j] = *(const float4*)(out + base + (size_t)(j * 32 + lane) * 4);
        sum += vals[j].x + vals[j].y + vals[j].z + vals[j].w;
        sq  += vals[j].x * vals[j].x + vals[j].y * vals[j].y
             + vals[j].z * vals[j].z + vals[j].w * vals[j].w;
    }
    #pragma unroll
    for (int o = 16; o > 0; o >>= 1) {
        sum += __shfl_xor_sync(0xffffffffu, sum, o);
        sq  += __shfl_xor_sync(0xffffffffu, sq,  o);
    }
    const float mean = sum * (1.f / 512.f);
    const float var  = sq * (1.f / 512.f) - mean * mean;
    const float rstd = rsqrtf(var + 1e-5f);

    #pragma unroll
    for (int j = 0; j < 4; j++) {
        int c = (j * 32 + lane) * 4;
        float4 g  = *(const float4*)(gamma + c);
        float4 bb = *(const float4*)(beta + c);
        float4 v;
        v.x = (vals[j].x - mean) * rstd * g.x + bb.x;
        v.y = (vals[j].y - mean) * rstd * g.y + bb.y;
        v.z = (vals[j].z - mean) * rstd * g.z + bb.z;
        v.w = (vals[j].w - mean) * rstd * g.w + bb.w;
        *(float4*)(out + base + c) = v;
    }
}

// ---------------------------------------------------------------------------
extern "C" void kernel_launch(void* const* d_in, const int* in_sizes, int n_in,
                              void* d_out, int out_size)
{
    const float* x     = (const float*)d_in[0];
    const float* P     = (const float*)d_in[1];
    const float* Wq    = (const float*)d_in[2];
    const float* Wk    = (const float*)d_in[3];
    const float* Wv    = (const float*)d_in[4];
    const float* Wo    = (const float*)d_in[5];
    const float* bo    = (const float*)d_in[6];
    const float* gamma = (const float*)d_in[7];
    const float* beta  = (const float*)d_in[8];
    float* out = (float*)d_out;

    void *pq, *pk, *pv, *pxh, *pxl, *pch, *pcl, *pwh, *pwl;
    cudaGetSymbolAddress(&pq,  g_q);
    cudaGetSymbolAddress(&pk,  g_k);
    cudaGetSymbolAddress(&pv,  g_v);
    cudaGetSymbolAddress(&pxh, g_xh);
    cudaGetSymbolAddress(&pxl, g_xl);
    cudaGetSymbolAddress(&pch, g_ch);
    cudaGetSymbolAddress(&pcl, g_cl);
    cudaGetSymbolAddress(&pwh, g_wh);
    cudaGetSymbolAddress(&pwl, g_wl);

    __nv_bfloat16* wh = (__nv_bfloat16*)pwh;
    __nv_bfloat16* wl = (__nv_bfloat16*)pwl;

    const int dsm = 2 * STAGE_BYTES;                // 110592
    cudaFuncSetAttribute(gemm_mma<0>, cudaFuncAttributeMaxDynamicSharedMemorySize, dsm);
    cudaFuncSetAttribute(gemm_mma<1>, cudaFuncAttributeMaxDynamicSharedMemorySize, dsm);

    // Splits
    dim3 gw(256, 4);
    wsplit_kernel<<<gw, 256>>>(Wq, Wk, Wv, Wo, wh, wl);
    const int nx4 = (int)((size_t)NROW * 512 / 4);
    split_kernel<<<(nx4 + 255) / 256, 256>>>(x, (__nv_bfloat16*)pxh,
                                             (__nv_bfloat16*)pxl, nx4);

    // Fused QKV projection: 12 col tiles over contiguous [Wq;Wk;Wv] rows
    dim3 gq(12, NROW / 128);
    gemm_mma<0><<<gq, 128, dsm>>>((const __nv_bfloat16*)pxh, (const __nv_bfloat16*)pxl,
                                  wh, wl,
                                  (float*)pq, (float*)pk, (float*)pv,
                                  nullptr, nullptr);

    dim3 ga(NSAMP, 2);
    attn_kernel<<<ga, 128>>>(
        (const float*)pq, (const float*)pk, (const float*)pv, P,
        (__nv_bfloat16*)pch, (__nv_bfloat16*)pcl);

    // fc_out + bias + residual
    dim3 go(4, NROW / 128);
    gemm_mma<1><<<go, 128, dsm>>>((const __nv_bfloat16*)pch, (const __nv_bfloat16*)pcl,
                                  wh + 3 * 262144, wl + 3 * 262144,
                                  out, nullptr, nullptr, bo, x);

    ln_kernel<<<NROW / 8, 256>>>(out, gamma, beta);
}

// round 13
// speedup vs baseline: 1.4850x; 1.4131x over previous
#include <cuda_runtime.h>
#include <cuda_bf16.h>
#include <cstdint>

// Problem constants
#define B_  32
#define S_  256
#define D_  17
#define M_  512
#define H_  8
#define DK_ 64
#define NROW  139264          // B*S*D rows of width 512
#define NSAMP 8192            // B*S

// ---------------------------------------------------------------------------
// Scratch (__device__ globals; allocation-free rule)
// g_xt / g_ct: fragment-major packed tf32 (fp32 storage) A operands.
// g_wt: fragment-major packed tf32 B operands for Wq,Wk,Wv,Wo (contiguous).
// ---------------------------------------------------------------------------
__device__ float g_q[(size_t)NROW * M_];
__device__ float g_k[(size_t)NROW * M_];
__device__ float g_v[(size_t)NROW * M_];
__device__ float g_xt[(size_t)NROW * M_];
__device__ float g_ct[(size_t)NROW * M_];
__device__ float g_wt[4 * 512 * 512];

// ---------------------------------------------------------------------------
// Helpers
// ---------------------------------------------------------------------------
__device__ __forceinline__ uint32_t smem_u32(const void* p) {
    uint32_t a;
    asm("{ .reg .u64 t; cvta.to.shared.u64 t, %1; cvt.u32.u64 %0, t; }"
        : "=r"(a) : "l"(p));
    return a;
}

__device__ __forceinline__ void cp16(uint32_t dst, const void* src) {
    asm volatile("cp.async.cg.shared.global [%0], [%1], 16;" :: "r"(dst), "l"(src));
}

__device__ __forceinline__ uint32_t f2tf32(float x) {
    uint32_t u;
    asm("cvt.rna.tf32.f32 %0, %1;" : "=r"(u) : "f"(x));
    return u;
}

__device__ __forceinline__ void lds128(uint32_t* r, uint32_t addr) {
    asm volatile("ld.shared.v4.b32 {%0,%1,%2,%3}, [%4];"
                 : "=r"(r[0]), "=r"(r[1]), "=r"(r[2]), "=r"(r[3]) : "r"(addr));
}

__device__ __forceinline__ void lds64(uint32_t* r, uint32_t addr) {
    asm volatile("ld.shared.v2.b32 {%0,%1}, [%2];"
                 : "=r"(r[0]), "=r"(r[1]) : "r"(addr));
}

__device__ __forceinline__ void mma_tf32(float* d, const uint32_t* a,
                                         uint32_t b0, uint32_t b1) {
    asm volatile(
        "mma.sync.aligned.m16n8k8.row.col.f32.tf32.tf32.f32 "
        "{%0,%1,%2,%3}, {%4,%5,%6,%7}, {%8,%9}, {%0,%1,%2,%3};"
        : "+f"(d[0]), "+f"(d[1]), "+f"(d[2]), "+f"(d[3])
        : "r"(a[0]), "r"(a[1]), "r"(a[2]), "r"(a[3]), "r"(b0), "r"(b1));
}

// ---------------------------------------------------------------------------
// Fragment-major packed layouts (m16n8k8 tf32):
//   A block (16 rows x 8 k) = 128 floats: At[((rt*64+kt)*32 + l)*4 + j]
//     j0:(row=l>>2,    col=l&3)   j1:(row=(l>>2)+8, col=l&3)
//     j2:(row=l>>2,    col=(l&3)+4) j3:((l>>2)+8,   (l&3)+4)
//   B block (8 n x 8 k) = 64 floats:  Bt[((nt*64+kt)*32 + l)*2 + j]
//     j0:(n=l>>2, k=l&3)   j1:(n=l>>2, k=(l&3)+4)
// GEMM: single-pass tf32, K=512, BK=32 (4 k-tiles/iter), 16 iters, 3 stages.
// BM=BN=128, 128 threads (4 warps 2x2), warp tile 64x64.
// ---------------------------------------------------------------------------
#define GITERS 16
#define GSTAGE 32768            // A 16KB + B 16KB per stage

__device__ __forceinline__ void gload_iter(
    int tid, uint32_t sbase, int rt0, int nt0, int it,
    const float* __restrict__ At, const float* __restrict__ Bt)
{
    const int kt0 = it * 4;
    #pragma unroll
    for (int t = 0; t < 8; t++) {                 // A: 8 row-tiles x 2KB
        int c = tid + t * 128;
        int i = c >> 7, rem = c & 127;
        cp16(sbase + i * 2048 + rem * 16,
             At + (((size_t)(rt0 + i) * 64 + kt0) << 7) + rem * 4);
    }
    const uint32_t sb2 = sbase + 16384;
    #pragma unroll
    for (int t = 0; t < 8; t++) {                 // B: 16 n-tiles x 1KB
        int c = tid + t * 128;
        int i = c >> 6, rem = c & 63;
        cp16(sb2 + i * 1024 + rem * 16,
             Bt + (((size_t)(nt0 + i) * 64 + kt0) << 6) + rem * 4);
    }
    asm volatile("cp.async.commit_group;");
}

template<int MODE>
__global__ __launch_bounds__(128)
void gemm_tf32(const float* __restrict__ At, const float* __restrict__ Bt,
               float* __restrict__ C0, float* __restrict__ C1,
               float* __restrict__ C2,
               const float* __restrict__ bias,
               const float* __restrict__ resid)
{
    extern __shared__ __align__(128) char smem[];

    const int tid = threadIdx.x;
    const int wid = tid >> 5;
    const int lid = tid & 31;
    const int c0 = blockIdx.x << 7;      // output col tile origin
    const int r0 = blockIdx.y << 7;      // output row tile origin
    const int m0 = (wid & 1) * 64;
    const int n0 = (wid >> 1) * 64;
    const int rt0 = r0 >> 4;             // 8 row-tiles per CTA
    const int nt0 = c0 >> 3;             // 16 n-tiles per CTA
    const uint32_t sb = smem_u32(smem);

    float acc[4][8][4];
    #pragma unroll
    for (int i = 0; i < 4; i++)
        #pragma unroll
        for (int j = 0; j < 8; j++)
            #pragma unroll
            for (int q = 0; q < 4; q++) acc[i][j][q] = 0.f;

    gload_iter(tid, sb, rt0, nt0, 0, At, Bt);
    gload_iter(tid, sb + GSTAGE, rt0, nt0, 1, At, Bt);

    const int mt0 = m0 >> 4;             // warp row-tile base (0 or 4)
    const int ntw = n0 >> 3;             // warp n-tile base (0 or 8)

    for (int it = 0; it < GITERS; it++) {
        if (it < GITERS - 1) asm volatile("cp.async.wait_group 1;");
        else                 asm volatile("cp.async.wait_group 0;");
        __syncthreads();

        if (it + 2 < GITERS)
            gload_iter(tid, sb + ((it + 2) % 3) * GSTAGE, rt0, nt0, it + 2, At, Bt);

        const uint32_t as = sb + (it % 3) * GSTAGE;
        const uint32_t bs = as + 16384;

        #pragma unroll
        for (int ktl = 0; ktl < 4; ktl++) {
            uint32_t a[4][4], b[8][2];
            #pragma unroll
            for (int mi = 0; mi < 4; mi++)
                lds128(a[mi], as + (uint32_t)(((mt0 + mi) * 4 + ktl) * 512 + lid * 16));
            #pragma unroll
            for (int nj = 0; nj < 8; nj++)
                lds64(b[nj], bs + (uint32_t)(((ntw + nj) * 4 + ktl) * 256 + lid * 8));
            #pragma unroll
            for (int mi = 0; mi < 4; mi++)
                #pragma unroll
                for (int nj = 0; nj < 8; nj++)
                    mma_tf32(acc[mi][nj], a[mi], b[nj][0], b[nj][1]);
        }
    }

    // Epilogue
    float* C;
    int col0;
    if (MODE == 0) {
        const int which = c0 >> 9;
        C = (which == 0) ? C0 : (which == 1) ? C1 : C2;
        col0 = c0 & 511;
    } else {
        C = C0;
        col0 = c0;
    }
    const int g  = lid >> 2;
    const int tg = lid & 3;
    #pragma unroll
    for (int mi = 0; mi < 4; mi++) {
        #pragma unroll
        for (int nj = 0; nj < 8; nj++) {
            const int r = r0 + m0 + mi * 16 + g;
            const int c = col0 + n0 + nj * 8 + tg * 2;
            float2 v0 = make_float2(acc[mi][nj][0], acc[mi][nj][1]);
            float2 v1 = make_float2(acc[mi][nj][2], acc[mi][nj][3]);
            if (MODE == 1) {
                const float2 bb = *(const float2*)(bias + c);
                const float2 q0 = *(const float2*)(resid + ((size_t)r << 9) + c);
                const float2 q1 = *(const float2*)(resid + ((size_t)(r + 8) << 9) + c);
                v0.x += bb.x + q0.x; v0.y += bb.y + q0.y;
                v1.x += bb.x + q1.x; v1.y += bb.y + q1.y;
            }
            *(float2*)(C + ((size_t)r << 9) + c)       = v0;
            *(float2*)(C + ((size_t)(r + 8) << 9) + c) = v1;
        }
    }
}

// ---------------------------------------------------------------------------
// Convert kernels: plain fp32 -> fragment-major packed tf32
// ---------------------------------------------------------------------------
__global__ __launch_bounds__(256)
void xconvert_kernel(const float* __restrict__ x, float* __restrict__ xt, int nquad)
{
    int qd = blockIdx.x * 256 + threadIdx.x;
    if (qd >= nquad) return;
    const int l  = qd & 31;
    const int kt = (qd >> 5) & 63;
    const int rt = qd >> 11;
    const int r  = rt * 16 + (l >> 2);
    const int c  = kt * 8 + (l & 3);
    float4 o;
    o.x = __uint_as_float(f2tf32(x[(size_t)r * 512 + c]));
    o.y = __uint_as_float(f2tf32(x[(size_t)(r + 8) * 512 + c]));
    o.z = __uint_as_float(f2tf32(x[(size_t)r * 512 + c + 4]));
    o.w = __uint_as_float(f2tf32(x[(size_t)(r + 8) * 512 + c + 4]));
    *(float4*)(xt + (size_t)qd * 4) = o;
}

__global__ __launch_bounds__(256)
void wconvert_kernel(const float* __restrict__ Wq, const float* __restrict__ Wk,
                     const float* __restrict__ Wv, const float* __restrict__ Wo,
                     float* __restrict__ wt)
{
    const int w = blockIdx.y;
    const float* src = (w == 0) ? Wq : (w == 1) ? Wk : (w == 2) ? Wv : Wo;
    int p = blockIdx.x * 256 + threadIdx.x;        // pair index < 131072
    const int l  = p & 31;
    const int kt = (p >> 5) & 63;
    const int nt = p >> 11;
    const int n  = nt * 8 + (l >> 2);
    const int c  = kt * 8 + (l & 3);
    float2 o;
    o.x = __uint_as_float(f2tf32(src[(size_t)n * 512 + c]));
    o.y = __uint_as_float(f2tf32(src[(size_t)n * 512 + c + 4]));
    *(float2*)(wt + (size_t)w * 262144 + (size_t)p * 2) = o;
}

// ---------------------------------------------------------------------------
// Attention (R12 structure): buffer-reuse cp.async staging, padded scores,
// 45KB smem -> 5 CTAs/SM. Output: packed tf32 ctx (fragment-major) for fc.
// ---------------------------------------------------------------------------
#define AB0 0
#define AB1 4624
#define ASS 9248                 // 4 heads * 400
#define ASP 10848                // 400
__global__ __launch_bounds__(128)
void attn_kernel(const float* __restrict__ q, const float* __restrict__ k,
                 const float* __restrict__ v, const float* __restrict__ P,
                 float* __restrict__ ct)
{
    __shared__ float sm[11248];  // 44992 bytes
    const int n  = blockIdx.x;
    const int hg = blockIdx.y;
    const int t  = threadIdx.x;
    const size_t base = (size_t)n * D_ * M_;
    const uint32_t smb = smem_u32(sm);

    // Phase 1: cp.async stage q -> BUF0, k -> BUF1; P LDGs overlap.
    #pragma unroll
    for (int u = 0; u < 9; u++) {
        int f = t + u * 128;
        if (f < 1088) {
            int d = f >> 6, hc = f & 63;
            int h = hc >> 4, c4 = hc & 15;
            size_t goff = base + (size_t)d * 512 + (hg * 4 + h) * 64 + c4 * 4;
            uint32_t soff = (uint32_t)(((h * 17 + d) * 68 + c4 * 4) * 4);
            cp16(smb + AB0 * 4 + soff, q + goff);
            cp16(smb + AB1 * 4 + soff, k + goff);
        }
    }
    asm volatile("cp.async.commit_group;");
    for (int f = t; f < 289; f += 128)
        sm[ASP + (f / 17) * 20 + (f % 17)] = P[f];
    asm volatile("cp.async.wait_group 0;");
    __syncthreads();

    // Phase 2: scores (padded 4x4 blocks)
    if (t < 100) {
        const int h = t / 25, blk = t % 25;
        const int d0 = (blk / 5) * 4, e0 = (blk % 5) * 4;
        const float* sq = sm + AB0 + (h * 17 + d0) * 68;
        const float* sk = sm + AB1 + (h * 17 + e0) * 68;
        float acc[4][4];
        #pragma unroll
        for (int i = 0; i < 4; i++)
            #pragma unroll
            for (int j = 0; j < 4; j++) acc[i][j] = 0.f;
        #pragma unroll 8
        for (int c4 = 0; c4 < 16; c4++) {
            float4 qa[4], kb[4];
            #pragma unroll
            for (int i = 0; i < 4; i++) qa[i] = *(const float4*)(sq + i * 68 + c4 * 4);
            #pragma unroll
            for (int j = 0; j < 4; j++) kb[j] = *(const float4*)(sk + j * 68 + c4 * 4);
            #pragma unroll
            for (int i = 0; i < 4; i++)
                #pragma unroll
                for (int j = 0; j < 4; j++)
                    acc[i][j] += qa[i].x * kb[j].x + qa[i].y * kb[j].y
                               + qa[i].z * kb[j].z + qa[i].w * kb[j].w;
        }
        float* ss = sm + ASS + h * 400;
        #pragma unroll
        for (int i = 0; i < 4; i++)
            #pragma unroll
            for (int j = 0; j < 4; j++)
                ss[(d0 + i) * 20 + e0 + j] =
                    acc[i][j] * 0.125f + sm[ASP + (d0 + i) * 20 + e0 + j];
    }
    __syncthreads();

    // Phase 3: cp.async v into BUF0; softmax overlaps.
    #pragma unroll
    for (int u = 0; u < 9; u++) {
        int f = t + u * 128;
        if (f < 1088) {
            int d = f >> 6, hc = f & 63;
            int h = hc >> 4, c4 = hc & 15;
            size_t goff = base + (size_t)d * 512 + (hg * 4 + h) * 64 + c4 * 4;
            uint32_t soff = (uint32_t)(((h * 17 + d) * 68 + c4 * 4) * 4);
            cp16(smb + AB0 * 4 + soff, v + goff);
        }
    }
    asm volatile("cp.async.commit_group;");
    if (t < 68) {
        float* row = sm + ASS + (t / 17) * 400 + (t % 17) * 20;
        float mx = -1e30f;
        #pragma unroll
        for (int e = 0; e < 17; e++) mx = fmaxf(mx, row[e]);
        float sum = 0.f;
        #pragma unroll
        for (int e = 0; e < 17; e++) {
            float ex = __expf(row[e] - mx);
            row[e] = ex;
            sum += ex;
        }
        float inv = 1.f / sum;
        #pragma unroll
        for (int e = 0; e < 17; e++) row[e] *= inv;
    }
    asm volatile("cp.async.wait_group 0;");
    __syncthreads();

    // Phase 4: ctx -> packed tf32 fragment-major output
    for (int task = t; task < 320; task += 128) {
        const int h = task / 80, rem = task % 80;
        const int d0 = (rem / 16) * 4, c0c = (rem % 16) * 4;
        const float* ss = sm + ASS + h * 400;
        const float* sv = sm + AB0 + h * 17 * 68 + c0c;
        float acc[4][4];
        #pragma unroll
        for (int i = 0; i < 4; i++)
            #pragma unroll
            for (int j = 0; j < 4; j++) acc[i][j] = 0.f;
        #pragma unroll
        for (int e = 0; e < 17; e++) {
            const float4 vv = *(const float4*)(sv + e * 68);
            #pragma unroll
            for (int i = 0; i < 4; i++) {
                const float w = ss[(d0 + i) * 20 + e];
                acc[i][0] += w * vv.x;
                acc[i][1] += w * vv.y;
                acc[i][2] += w * vv.z;
                acc[i][3] += w * vv.w;
            }
        }
        const int cbase = (hg * 4 + h) * 64 + c0c;     // col of element 0
        const int kt = cbase >> 3;
        const int jhi = ((cbase & 7) >= 4) ? 2 : 0;    // constant across 4 cols
        #pragma unroll
        for (int i = 0; i < 4; i++) {
            const int d = d0 + i;
            if (d < 17) {
                const int r = n * 17 + d;
                const int rt = r >> 4, rr = r & 15;
                const int j = ((rr >> 3) & 1) | jhi;
                const int l0 = (rr & 7) * 4;
                float* op = ct + (((size_t)rt * 64 + kt) * 32 + l0) * 4 + j;
                #pragma unroll
                for (int jj = 0; jj < 4; jj++)
                    op[jj * 4] = __uint_as_float(f2tf32(acc[i][jj]));
            }
        }
    }
}

// ---------------------------------------------------------------------------
// In-place LayerNorm (warp per row, width 512), eps = 1e-5
// ---------------------------------------------------------------------------
__global__ __launch_bounds__(256)
void ln_kernel(float* __restrict__ out, const float* __restrict__ gamma,
               const float* __restrict__ beta)
{
    const int row  = blockIdx.x * 8 + (threadIdx.x >> 5);
    const int lane = threadIdx.x & 31;
    const size_t base = (size_t)row * 512;

    float4 vals[4];
    float sum = 0.f, sq = 0.f;
    #pragma unroll
    for (int j = 0; j < 4; j++) {
        vals[j] = *(const float4*)(out + base + (size_t)(j * 32 + lane) * 4);
        sum += vals[j].x + vals[j].y + vals[j].z + vals[j].w;
        sq  += vals[j].x * vals[j].x + vals[j].y * vals[j].y
             + vals[j].z * vals[j].z + vals[j].w * vals[j].w;
    }
    #pragma unroll
    for (int o = 16; o > 0; o >>= 1) {
        sum += __shfl_xor_sync(0xffffffffu, sum, o);
        sq  += __shfl_xor_sync(0xffffffffu, sq,  o);
    }
    const float mean = sum * (1.f / 512.f);
    const float var  = sq * (1.f / 512.f) - mean * mean;
    const float rstd = rsqrtf(var + 1e-5f);

    #pragma unroll
    for (int j = 0; j < 4; j++) {
        int c = (j * 32 + lane) * 4;
        float4 g  = *(const float4*)(gamma + c);
        float4 bb = *(const float4*)(beta + c);
        float4 v;
        v.x = (vals[j].x - mean) * rstd * g.x + bb.x;
        v.y = (vals[j].y - mean) * rstd * g.y + bb.y;
        v.z = (vals[j].z - mean) * rstd * g.z + bb.z;
        v.w = (vals[j].w - mean) * rstd * g.w + bb.w;
        *(float4*)(out + base + c) = v;
    }
}

// ---------------------------------------------------------------------------
extern "C" void kernel_launch(void* const* d_in, const int* in_sizes, int n_in,
                              void* d_out, int out_size)
{
    const float* x     = (const float*)d_in[0];
    const float* P     = (const float*)d_in[1];
    const float* Wq    = (const float*)d_in[2];
    const float* Wk    = (const float*)d_in[3];
    const float* Wv    = (const float*)d_in[4];
    const float* Wo    = (const float*)d_in[5];
    const float* bo    = (const float*)d_in[6];
    const float* gamma = (const float*)d_in[7];
    const float* beta  = (const float*)d_in[8];
    float* out = (float*)d_out;

    void *pq, *pk, *pv, *pxt, *pct, *pwt;
    cudaGetSymbolAddress(&pq,  g_q);
    cudaGetSymbolAddress(&pk,  g_k);
    cudaGetSymbolAddress(&pv,  g_v);
    cudaGetSymbolAddress(&pxt, g_xt);
    cudaGetSymbolAddress(&pct, g_ct);
    cudaGetSymbolAddress(&pwt, g_wt);

    float* wt = (float*)pwt;

    const int dsm = 3 * GSTAGE;                     // 98304
    cudaFuncSetAttribute(gemm_tf32<0>, cudaFuncAttributeMaxDynamicSharedMemorySize, dsm);
    cudaFuncSetAttribute(gemm_tf32<1>, cudaFuncAttributeMaxDynamicSharedMemorySize, dsm);

    // Converts (plain fp32 -> packed tf32 fragment-major)
    dim3 gw(512, 4);                                // 131072 pairs per W
    wconvert_kernel<<<gw, 256>>>(Wq, Wk, Wv, Wo, wt);
    const int nquad = NROW * 512 / 4;               // 17,825,792
    xconvert_kernel<<<(nquad + 255) / 256, 256>>>(x, (float*)pxt, nquad);

    // Fused QKV projection: 12 col tiles over packed [Wq;Wk;Wv]
    dim3 gq(12, NROW / 128);
    gemm_tf32<0><<<gq, 128, dsm>>>((const float*)pxt, wt,
                                   (float*)pq, (float*)pk, (float*)pv,
                                   nullptr, nullptr);

    dim3 ga(NSAMP, 2);
    attn_kernel<<<ga, 128>>>(
        (const float*)pq, (const float*)pk, (const float*)pv, P, (float*)pct);

    // fc_out + bias + residual
    dim3 go(4, NROW / 128);
    gemm_tf32<1><<<go, 128, dsm>>>((const float*)pct, wt + 3 * 262144,
                                   out, nullptr, nullptr, bo, x);

    ln_kernel<<<NROW / 8, 256>>>(out, gamma, beta);
}

// round 14
// speedup vs baseline: 2.0203x; 1.3605x over previous
#include <cuda_runtime.h>
#include <cuda_fp16.h>
#include <cstdint>

// Problem constants
#define B_  32
#define S_  256
#define D_  17
#define M_  512
#define H_  8
#define DK_ 64
#define NROW  139264          // B*S*D rows of width 512
#define NSAMP 8192            // B*S

// ---------------------------------------------------------------------------
// Scratch (__device__ globals; allocation-free rule)
// ---------------------------------------------------------------------------
__device__ float g_q[(size_t)NROW * M_];
__device__ float g_k[(size_t)NROW * M_];
__device__ float g_v[(size_t)NROW * M_];
__device__ __half g_xh[(size_t)NROW * M_];      // x in fp16
__device__ __half g_ch[(size_t)NROW * M_];      // ctx in fp16
__device__ __half g_wh[4 * 512 * 512];          // Wq,Wk,Wv,Wo fp16 (contiguous)

// ---------------------------------------------------------------------------
// Helpers
// ---------------------------------------------------------------------------
__device__ __forceinline__ uint32_t smem_u32(const void* p) {
    uint32_t a;
    asm("{ .reg .u64 t; cvta.to.shared.u64 t, %1; cvt.u32.u64 %0, t; }"
        : "=r"(a) : "l"(p));
    return a;
}

__device__ __forceinline__ void cp16(uint32_t dst, const void* src) {
    asm volatile("cp.async.cg.shared.global [%0], [%1], 16;" :: "r"(dst), "l"(src));
}

__device__ __forceinline__ void ldmx4(uint32_t* r, uint32_t addr) {
    asm volatile("ldmatrix.sync.aligned.m8n8.x4.shared.b16 {%0,%1,%2,%3}, [%4];"
                 : "=r"(r[0]), "=r"(r[1]), "=r"(r[2]), "=r"(r[3]) : "r"(addr));
}

__device__ __forceinline__ void mma_f16(float* d, const uint32_t* a,
                                        uint32_t b0, uint32_t b1) {
    asm volatile(
        "mma.sync.aligned.m16n8k16.row.col.f32.f16.f16.f32 "
        "{%0,%1,%2,%3}, {%4,%5,%6,%7}, {%8,%9}, {%0,%1,%2,%3};"
        : "+f"(d[0]), "+f"(d[1]), "+f"(d[2]), "+f"(d[3])
        : "r"(a[0]), "r"(a[1]), "r"(a[2]), "r"(a[3]), "r"(b0), "r"(b1));
}

// ---------------------------------------------------------------------------
// Single-pass fp16 GEMM on HMMA (R10 skeleton, one operand pass):
// C[r,c] = sum_k A[r,k] * W[c,k],  K=512, BK=64/iter, 8 iters, 3 stages.
// BM=BN=128, 128 threads (4 warps 2x2), warp tile 64x64.
// smem rows padded to 144B -> conflict-free ldmatrix.
// MODE 0: fused q/k/v output (select by col tile). MODE 1: +bias+resid.
// ---------------------------------------------------------------------------
#define ITERS 8
#define ROWB 144
#define STAGE_BYTES (256 * ROWB)    // A(128 rows) + B(128 rows)
#define STAGES 3

__device__ __forceinline__ void load_iter(
    int tid, uint32_t sbase, int r0, int c0, int it,
    const __half* __restrict__ A, const __half* __restrict__ B)
{
    const int kk = it * 64;
    #pragma unroll
    for (int t = 0; t < 8; t++) {                 // A: 128 rows x 128B
        int f = tid + t * 128;
        int row = f >> 3, ch = f & 7;
        cp16(sbase + row * ROWB + ch * 16, A + ((size_t)(r0 + row) << 9) + kk + ch * 8);
    }
    const uint32_t b0 = sbase + 128 * ROWB;
    #pragma unroll
    for (int t = 0; t < 8; t++) {                 // B: 128 rows x 128B
        int f = tid + t * 128;
        int row = f >> 3, ch = f & 7;
        cp16(b0 + row * ROWB + ch * 16, B + ((size_t)(c0 + row) << 9) + kk + ch * 8);
    }
    asm volatile("cp.async.commit_group;");
}

template<int MODE>
__global__ __launch_bounds__(128)
void gemm_f16(const __half* __restrict__ A, const __half* __restrict__ W,
              float* __restrict__ C0, float* __restrict__ C1,
              float* __restrict__ C2,
              const float* __restrict__ bias,
              const float* __restrict__ resid)
{
    extern __shared__ __align__(128) char smem[];

    const int tid = threadIdx.x;
    const int wid = tid >> 5;
    const int lid = tid & 31;
    const int c0 = blockIdx.x << 7;    // col tile (fast dim -> A L2 reuse)
    const int r0 = blockIdx.y << 7;
    const int m0 = (wid & 1) * 64;
    const int n0 = (wid >> 1) * 64;
    const uint32_t sb = smem_u32(smem);

    float acc[4][8][4];
    #pragma unroll
    for (int i = 0; i < 4; i++)
        #pragma unroll
        for (int j = 0; j < 8; j++)
            #pragma unroll
            for (int q = 0; q < 4; q++) acc[i][j][q] = 0.f;

    load_iter(tid, sb, r0, c0, 0, A, W);
    load_iter(tid, sb + STAGE_BYTES, r0, c0, 1, A, W);

    const uint32_t a_off = (uint32_t)((m0 + (lid & 15)) * ROWB + ((lid >> 4) << 4));
    const uint32_t b_off = (uint32_t)((n0 + (lid & 7) + ((lid >> 4) << 3)) * ROWB
                                      + (((lid >> 3) & 1) << 4));

    for (int it = 0; it < ITERS; it++) {
        if (it < ITERS - 1) asm volatile("cp.async.wait_group 1;");
        else                asm volatile("cp.async.wait_group 0;");
        __syncthreads();

        if (it + 2 < ITERS)
            load_iter(tid, sb + ((it + 2) % STAGES) * STAGE_BYTES, r0, c0,
                      it + 2, A, W);

        const uint32_t as = sb + (it % STAGES) * STAGE_BYTES;
        const uint32_t bs = as + 128 * ROWB;

        #pragma unroll
        for (int kt = 0; kt < 4; kt++) {
            uint32_t a[4][4], b[4][4];
            #pragma unroll
            for (int mi = 0; mi < 4; mi++)
                ldmx4(a[mi], as + a_off + (uint32_t)(mi * 16 * ROWB + kt * 32));
            #pragma unroll
            for (int nj = 0; nj < 4; nj++)
                ldmx4(b[nj], bs + b_off + (uint32_t)(nj * 16 * ROWB + kt * 32));
            #pragma unroll
            for (int mi = 0; mi < 4; mi++)
                #pragma unroll
                for (int ni = 0; ni < 8; ni++)
                    mma_f16(acc[mi][ni], a[mi],
                            b[ni >> 1][(ni & 1) * 2], b[ni >> 1][(ni & 1) * 2 + 1]);
        }
    }

    // Epilogue
    float* C;
    int col0;
    if (MODE == 0) {
        const int which = c0 >> 9;
        C = (which == 0) ? C0 : (which == 1) ? C1 : C2;
        col0 = c0 & 511;
    } else {
        C = C0;
        col0 = c0;
    }
    const int g  = lid >> 2;
    const int tg = lid & 3;
    #pragma unroll
    for (int mi = 0; mi < 4; mi++) {
        #pragma unroll
        for (int ni = 0; ni < 8; ni++) {
            const int r = r0 + m0 + mi * 16 + g;
            const int c = col0 + n0 + ni * 8 + tg * 2;
            float2 v0 = make_float2(acc[mi][ni][0], acc[mi][ni][1]);
            float2 v1 = make_float2(acc[mi][ni][2], acc[mi][ni][3]);
            if (MODE == 1) {
                const float2 bb = *(const float2*)(bias + c);
                const float2 q0 = *(const float2*)(resid + ((size_t)r << 9) + c);
                const float2 q1 = *(const float2*)(resid + ((size_t)(r + 8) << 9) + c);
                v0.x += bb.x + q0.x; v0.y += bb.y + q0.y;
                v1.x += bb.x + q1.x; v1.y += bb.y + q1.y;
            }
            *(float2*)(C + ((size_t)r << 9) + c)       = v0;
            *(float2*)(C + ((size_t)(r + 8) << 9) + c) = v1;
        }
    }
}

// ---------------------------------------------------------------------------
// fp32 -> fp16 converts
// ---------------------------------------------------------------------------
__global__ __launch_bounds__(256)
void wconvert_kernel(const float* __restrict__ Wq, const float* __restrict__ Wk,
                     const float* __restrict__ Wv, const float* __restrict__ Wo,
                     __half* __restrict__ wh)
{
    const int w = blockIdx.y;
    const float* src = (w == 0) ? Wq : (w == 1) ? Wk : (w == 2) ? Wv : Wo;
    const int i = blockIdx.x * 256 + threadIdx.x;      // < 65536 float4s
    float4 v = ((const float4*)src)[i];
    __half2* hp = (__half2*)(wh + (size_t)w * 262144);
    hp[2 * i]     = __half2(__float2half(v.x), __float2half(v.y));
    hp[2 * i + 1] = __half2(__float2half(v.z), __float2half(v.w));
}

__global__ __launch_bounds__(256)
void xconvert_kernel(const float* __restrict__ in, __half* __restrict__ out, int n4)
{
    int i = blockIdx.x * 256 + threadIdx.x;
    if (i >= n4) return;
    float4 v = ((const float4*)in)[i];
    __half2* hp = (__half2*)out;
    hp[2 * i]     = __half2(__float2half(v.x), __float2half(v.y));
    hp[2 * i + 1] = __half2(__float2half(v.z), __float2half(v.w));
}

// ---------------------------------------------------------------------------
// Attention (R12 structure): buffer-reuse cp.async staging, padded scores,
// 45KB smem -> 5 CTAs/SM. Output: row-major fp16 ctx (contiguous 8B stores).
// ---------------------------------------------------------------------------
#define AB0 0
#define AB1 4624
#define ASS 9248                 // 4 heads * 400
#define ASP 10848                // 400
__global__ __launch_bounds__(128)
void attn_kernel(const float* __restrict__ q, const float* __restrict__ k,
                 const float* __restrict__ v, const float* __restrict__ P,
                 __half* __restrict__ ch)
{
    __shared__ float sm[11248];  // 44992 bytes
    const int n  = blockIdx.x;
    const int hg = blockIdx.y;
    const int t  = threadIdx.x;
    const size_t base = (size_t)n * D_ * M_;
    const uint32_t smb = smem_u32(sm);

    // Phase 1: cp.async stage q -> BUF0, k -> BUF1; P LDGs overlap.
    #pragma unroll
    for (int u = 0; u < 9; u++) {
        int f = t + u * 128;
        if (f < 1088) {
            int d = f >> 6, hc = f & 63;
            int h = hc >> 4, c4 = hc & 15;
            size_t goff = base + (size_t)d * 512 + (hg * 4 + h) * 64 + c4 * 4;
            uint32_t soff = (uint32_t)(((h * 17 + d) * 68 + c4 * 4) * 4);
            cp16(smb + AB0 * 4 + soff, q + goff);
            cp16(smb + AB1 * 4 + soff, k + goff);
        }
    }
    asm volatile("cp.async.commit_group;");
    for (int f = t; f < 289; f += 128)
        sm[ASP + (f / 17) * 20 + (f % 17)] = P[f];
    asm volatile("cp.async.wait_group 0;");
    __syncthreads();

    // Phase 2: scores (padded 4x4 blocks)
    if (t < 100) {
        const int h = t / 25, blk = t % 25;
        const int d0 = (blk / 5) * 4, e0 = (blk % 5) * 4;
        const float* sq = sm + AB0 + (h * 17 + d0) * 68;
        const float* sk = sm + AB1 + (h * 17 + e0) * 68;
        float acc[4][4];
        #pragma unroll
        for (int i = 0; i < 4; i++)
            #pragma unroll
            for (int j = 0; j < 4; j++) acc[i][j] = 0.f;
        #pragma unroll 8
        for (int c4 = 0; c4 < 16; c4++) {
            float4 qa[4], kb[4];
            #pragma unroll
            for (int i = 0; i < 4; i++) qa[i] = *(const float4*)(sq + i * 68 + c4 * 4);
            #pragma unroll
            for (int j = 0; j < 4; j++) kb[j] = *(const float4*)(sk + j * 68 + c4 * 4);
            #pragma unroll
            for (int i = 0; i < 4; i++)
                #pragma unroll
                for (int j = 0; j < 4; j++)
                    acc[i][j] += qa[i].x * kb[j].x + qa[i].y * kb[j].y
                               + qa[i].z * kb[j].z + qa[i].w * kb[j].w;
        }
        float* ss = sm + ASS + h * 400;
        #pragma unroll
        for (int i = 0; i < 4; i++)
            #pragma unroll
            for (int j = 0; j < 4; j++)
                ss[(d0 + i) * 20 + e0 + j] =
                    acc[i][j] * 0.125f + sm[ASP + (d0 + i) * 20 + e0 + j];
    }
    __syncthreads();

    // Phase 3: cp.async v into BUF0; softmax overlaps.
    #pragma unroll
    for (int u = 0; u < 9; u++) {
        int f = t + u * 128;
        if (f < 1088) {
            int d = f >> 6, hc = f & 63;
            int h = hc >> 4, c4 = hc & 15;
            size_t goff = base + (size_t)d * 512 + (hg * 4 + h) * 64 + c4 * 4;
            uint32_t soff = (uint32_t)(((h * 17 + d) * 68 + c4 * 4) * 4);
            cp16(smb + AB0 * 4 + soff, v + goff);
        }
    }
    asm volatile("cp.async.commit_group;");
    if (t < 68) {
        float* row = sm + ASS + (t / 17) * 400 + (t % 17) * 20;
        float mx = -1e30f;
        #pragma unroll
        for (int e = 0; e < 17; e++) mx = fmaxf(mx, row[e]);
        float sum = 0.f;
        #pragma unroll
        for (int e = 0; e < 17; e++) {
            float ex = __expf(row[e] - mx);
            row[e] = ex;
            sum += ex;
        }
        float inv = 1.f / sum;
        #pragma unroll
        for (int e = 0; e < 17; e++) row[e] *= inv;
    }
    asm volatile("cp.async.wait_group 0;");
    __syncthreads();

    // Phase 4: ctx -> row-major fp16 (contiguous 8B stores)
    for (int task = t; task < 320; task += 128) {
        const int h = task / 80, rem = task % 80;
        const int d0 = (rem / 16) * 4, c0c = (rem % 16) * 4;
        const float* ss = sm + ASS + h * 400;
        const float* sv = sm + AB0 + h * 17 * 68 + c0c;
        float acc[4][4];
        #pragma unroll
        for (int i = 0; i < 4; i++)
            #pragma unroll
            for (int j = 0; j < 4; j++) acc[i][j] = 0.f;
        #pragma unroll
        for (int e = 0; e < 17; e++) {
            const float4 vv = *(const float4*)(sv + e * 68);
            #pragma unroll
            for (int i = 0; i < 4; i++) {
                const float w = ss[(d0 + i) * 20 + e];
                acc[i][0] += w * vv.x;
                acc[i][1] += w * vv.y;
                acc[i][2] += w * vv.z;
                acc[i][3] += w * vv.w;
            }
        }
        #pragma unroll
        for (int i = 0; i < 4; i++) {
            const int d = d0 + i;
            if (d < 17) {
                const size_t off = base + (size_t)d * 512 + (hg * 4 + h) * 64 + c0c;
                __half hh[4];
                #pragma unroll
                for (int j = 0; j < 4; j++) hh[j] = __float2half(acc[i][j]);
                *(uint2*)(ch + off) = *(uint2*)hh;
            }
        }
    }
}

// ---------------------------------------------------------------------------
// In-place LayerNorm (warp per row, width 512), eps = 1e-5
// ---------------------------------------------------------------------------
__global__ __launch_bounds__(256)
void ln_kernel(float* __restrict__ out, const float* __restrict__ gamma,
               const float* __restrict__ beta)
{
    const int row  = blockIdx.x * 8 + (threadIdx.x >> 5);
    const int lane = threadIdx.x & 31;
    const size_t base = (size_t)row * 512;

    float4 vals[4];
    float sum = 0.f, sq = 0.f;
    #pragma unroll
    for (int j = 0; j < 4; j++) {
        vals[j] = *(const float4*)(out + base + (size_t)(j * 32 + lane) * 4);
        sum += vals[j].x + vals[j].y + vals[j].z + vals[j].w;
        sq  += vals[j].x * vals[j].x + vals[j].y * vals[j].y
             + vals[j].z * vals[j].z + vals[j].w * vals[j].w;
    }
    #pragma unroll
    for (int o = 16; o > 0; o >>= 1) {
        sum += __shfl_xor_sync(0xffffffffu, sum, o);
        sq  += __shfl_xor_sync(0xffffffffu, sq,  o);
    }
    const float mean = sum * (1.f / 512.f);
    const float var  = sq * (1.f / 512.f) - mean * mean;
    const float rstd = rsqrtf(var + 1e-5f);

    #pragma unroll
    for (int j = 0; j < 4; j++) {
        int c = (j * 32 + lane) * 4;
        float4 g  = *(const float4*)(gamma + c);
        float4 bb = *(const float4*)(beta + c);
        float4 v;
        v.x = (vals[j].x - mean) * rstd * g.x + bb.x;
        v.y = (vals[j].y - mean) * rstd * g.y + bb.y;
        v.z = (vals[j].z - mean) * rstd * g.z + bb.z;
        v.w = (vals[j].w - mean) * rstd * g.w + bb.w;
        *(float4*)(out + base + c) = v;
    }
}

// ---------------------------------------------------------------------------
extern "C" void kernel_launch(void* const* d_in, const int* in_sizes, int n_in,
                              void* d_out, int out_size)
{
    const float* x     = (const float*)d_in[0];
    const float* P     = (const float*)d_in[1];
    const float* Wq    = (const float*)d_in[2];
    const float* Wk    = (const float*)d_in[3];
    const float* Wv    = (const float*)d_in[4];
    const float* Wo    = (const float*)d_in[5];
    const float* bo    = (const float*)d_in[6];
    const float* gamma = (const float*)d_in[7];
    const float* beta  = (const float*)d_in[8];
    float* out = (float*)d_out;

    void *pq, *pk, *pv, *pxh, *pch, *pwh;
    cudaGetSymbolAddress(&pq,  g_q);
    cudaGetSymbolAddress(&pk,  g_k);
    cudaGetSymbolAddress(&pv,  g_v);
    cudaGetSymbolAddress(&pxh, g_xh);
    cudaGetSymbolAddress(&pch, g_ch);
    cudaGetSymbolAddress(&pwh, g_wh);

    __half* wh = (__half*)pwh;

    const int dsm = STAGES * STAGE_BYTES;           // 110592
    cudaFuncSetAttribute(gemm_f16<0>, cudaFuncAttributeMaxDynamicSharedMemorySize, dsm);
    cudaFuncSetAttribute(gemm_f16<1>, cudaFuncAttributeMaxDynamicSharedMemorySize, dsm);

    // Converts
    dim3 gw(256, 4);
    wconvert_kernel<<<gw, 256>>>(Wq, Wk, Wv, Wo, wh);
    const int nx4 = (int)((size_t)NROW * 512 / 4);
    xconvert_kernel<<<(nx4 + 255) / 256, 256>>>(x, (__half*)pxh, nx4);

    // Fused QKV projection: 12 col tiles over contiguous [Wq;Wk;Wv] rows
    dim3 gq(12, NROW / 128);
    gemm_f16<0><<<gq, 128, dsm>>>((const __half*)pxh, wh,
                                  (float*)pq, (float*)pk, (float*)pv,
                                  nullptr, nullptr);

    dim3 ga(NSAMP, 2);
    attn_kernel<<<ga, 128>>>(
        (const float*)pq, (const float*)pk, (const float*)pv, P, (__half*)pch);

    // fc_out + bias + residual
    dim3 go(4, NROW / 128);
    gemm_f16<1><<<go, 128, dsm>>>((const __half*)pch, wh + 3 * 262144,
                                  out, nullptr, nullptr, bo, x);

    ln_kernel<<<NROW / 8, 256>>>(out, gamma, beta);
}

// round 15
// speedup vs baseline: 2.1423x; 1.0604x over previous
#include <cuda_runtime.h>
#include <cuda_fp16.h>
#include <cstdint>

// Problem constants
#define B_  32
#define S_  256
#define D_  17
#define M_  512
#define H_  8
#define DK_ 64
#define NROW  139264          // B*S*D rows of width 512
#define NSAMP 8192            // B*S

// ---------------------------------------------------------------------------
// Scratch (__device__ globals; allocation-free rule)
// ---------------------------------------------------------------------------
__device__ __half g_q[(size_t)NROW * M_];
__device__ __half g_k[(size_t)NROW * M_];
__device__ __half g_v[(size_t)NROW * M_];
__device__ __half g_xh[(size_t)NROW * M_];      // x in fp16
__device__ __half g_ch[(size_t)NROW * M_];      // ctx in fp16
__device__ __half g_wh[4 * 512 * 512];          // Wq,Wk,Wv,Wo fp16 (contiguous)

// ---------------------------------------------------------------------------
// Helpers
// ---------------------------------------------------------------------------
__device__ __forceinline__ uint32_t smem_u32(const void* p) {
    uint32_t a;
    asm("{ .reg .u64 t; cvta.to.shared.u64 t, %1; cvt.u32.u64 %0, t; }"
        : "=r"(a) : "l"(p));
    return a;
}

__device__ __forceinline__ void cp16(uint32_t dst, const void* src) {
    asm volatile("cp.async.cg.shared.global [%0], [%1], 16;" :: "r"(dst), "l"(src));
}

__device__ __forceinline__ void ldmx4(uint32_t* r, uint32_t addr) {
    asm volatile("ldmatrix.sync.aligned.m8n8.x4.shared.b16 {%0,%1,%2,%3}, [%4];"
                 : "=r"(r[0]), "=r"(r[1]), "=r"(r[2]), "=r"(r[3]) : "r"(addr));
}

__device__ __forceinline__ void mma_f16(float* d, const uint32_t* a,
                                        uint32_t b0, uint32_t b1) {
    asm volatile(
        "mma.sync.aligned.m16n8k16.row.col.f32.f16.f16.f32 "
        "{%0,%1,%2,%3}, {%4,%5,%6,%7}, {%8,%9}, {%0,%1,%2,%3};"
        : "+f"(d[0]), "+f"(d[1]), "+f"(d[2]), "+f"(d[3])
        : "r"(a[0]), "r"(a[1]), "r"(a[2]), "r"(a[3]), "r"(b0), "r"(b1));
}

// ---------------------------------------------------------------------------
// Single-pass fp16 GEMM on HMMA (R14 skeleton):
// C[r,c] = sum_k A[r,k] * W[c,k],  K=512, BK=64/iter, 8 iters, 3 stages.
// BM=BN=128, 128 threads (4 warps 2x2), warp tile 64x64.
// MODE 0: fused q/k/v fp16 output. MODE 1: fp32 out + bias + resid.
// ---------------------------------------------------------------------------
#define ITERS 8
#define ROWB 144
#define STAGE_BYTES (256 * ROWB)
#define STAGES 3

__device__ __forceinline__ void load_iter(
    int tid, uint32_t sbase, int r0, int c0, int it,
    const __half* __restrict__ A, const __half* __restrict__ B)
{
    const int kk = it * 64;
    #pragma unroll
    for (int t = 0; t < 8; t++) {                 // A: 128 rows x 128B
        int f = tid + t * 128;
        int row = f >> 3, ch = f & 7;
        cp16(sbase + row * ROWB + ch * 16, A + ((size_t)(r0 + row) << 9) + kk + ch * 8);
    }
    const uint32_t b0 = sbase + 128 * ROWB;
    #pragma unroll
    for (int t = 0; t < 8; t++) {                 // B: 128 rows x 128B
        int f = tid + t * 128;
        int row = f >> 3, ch = f & 7;
        cp16(b0 + row * ROWB + ch * 16, B + ((size_t)(c0 + row) << 9) + kk + ch * 8);
    }
    asm volatile("cp.async.commit_group;");
}

template<int MODE>
__global__ __launch_bounds__(128)
void gemm_f16(const __half* __restrict__ A, const __half* __restrict__ W,
              void* __restrict__ O0, void* __restrict__ O1, void* __restrict__ O2,
              const float* __restrict__ bias,
              const float* __restrict__ resid)
{
    extern __shared__ __align__(128) char smem[];

    const int tid = threadIdx.x;
    const int wid = tid >> 5;
    const int lid = tid & 31;
    const int c0 = blockIdx.x << 7;    // col tile (fast dim -> A L2 reuse)
    const int r0 = blockIdx.y << 7;
    const int m0 = (wid & 1) * 64;
    const int n0 = (wid >> 1) * 64;
    const uint32_t sb = smem_u32(smem);

    float acc[4][8][4];
    #pragma unroll
    for (int i = 0; i < 4; i++)
        #pragma unroll
        for (int j = 0; j < 8; j++)
            #pragma unroll
            for (int q = 0; q < 4; q++) acc[i][j][q] = 0.f;

    load_iter(tid, sb, r0, c0, 0, A, W);
    load_iter(tid, sb + STAGE_BYTES, r0, c0, 1, A, W);

    const uint32_t a_off = (uint32_t)((m0 + (lid & 15)) * ROWB + ((lid >> 4) << 4));
    const uint32_t b_off = (uint32_t)((n0 + (lid & 7) + ((lid >> 4) << 3)) * ROWB
                                      + (((lid >> 3) & 1) << 4));

    for (int it = 0; it < ITERS; it++) {
        if (it < ITERS - 1) asm volatile("cp.async.wait_group 1;");
        else                asm volatile("cp.async.wait_group 0;");
        __syncthreads();

        if (it + 2 < ITERS)
            load_iter(tid, sb + ((it + 2) % STAGES) * STAGE_BYTES, r0, c0,
                      it + 2, A, W);

        const uint32_t as = sb + (it % STAGES) * STAGE_BYTES;
        const uint32_t bs = as + 128 * ROWB;

        #pragma unroll
        for (int kt = 0; kt < 4; kt++) {
            uint32_t a[4][4], b[4][4];
            #pragma unroll
            for (int mi = 0; mi < 4; mi++)
                ldmx4(a[mi], as + a_off + (uint32_t)(mi * 16 * ROWB + kt * 32));
            #pragma unroll
            for (int nj = 0; nj < 4; nj++)
                ldmx4(b[nj], bs + b_off + (uint32_t)(nj * 16 * ROWB + kt * 32));
            #pragma unroll
            for (int mi = 0; mi < 4; mi++)
                #pragma unroll
                for (int ni = 0; ni < 8; ni++)
                    mma_f16(acc[mi][ni], a[mi],
                            b[ni >> 1][(ni & 1) * 2], b[ni >> 1][(ni & 1) * 2 + 1]);
        }
    }

    // Epilogue
    const int g  = lid >> 2;
    const int tg = lid & 3;
    if (MODE == 0) {
        const int which = c0 >> 9;
        __half* C = (__half*)((which == 0) ? O0 : (which == 1) ? O1 : O2);
        const int col0 = c0 & 511;
        #pragma unroll
        for (int mi = 0; mi < 4; mi++) {
            #pragma unroll
            for (int ni = 0; ni < 8; ni++) {
                const int r = r0 + m0 + mi * 16 + g;
                const int c = col0 + n0 + ni * 8 + tg * 2;
                *(__half2*)(C + ((size_t)r << 9) + c) =
                    __floats2half2_rn(acc[mi][ni][0], acc[mi][ni][1]);
                *(__half2*)(C + ((size_t)(r + 8) << 9) + c) =
                    __floats2half2_rn(acc[mi][ni][2], acc[mi][ni][3]);
            }
        }
    } else {
        float* C = (float*)O0;
        #pragma unroll
        for (int mi = 0; mi < 4; mi++) {
            #pragma unroll
            for (int ni = 0; ni < 8; ni++) {
                const int r = r0 + m0 + mi * 16 + g;
                const int c = c0 + n0 + ni * 8 + tg * 2;
                float2 v0 = make_float2(acc[mi][ni][0], acc[mi][ni][1]);
                float2 v1 = make_float2(acc[mi][ni][2], acc[mi][ni][3]);
                const float2 bb = *(const float2*)(bias + c);
                const float2 q0 = *(const float2*)(resid + ((size_t)r << 9) + c);
                const float2 q1 = *(const float2*)(resid + ((size_t)(r + 8) << 9) + c);
                v0.x += bb.x + q0.x; v0.y += bb.y + q0.y;
                v1.x += bb.x + q1.x; v1.y += bb.y + q1.y;
                *(float2*)(C + ((size_t)r << 9) + c)       = v0;
                *(float2*)(C + ((size_t)(r + 8) << 9) + c) = v1;
            }
        }
    }
}

// ---------------------------------------------------------------------------
// Merged convert: x (nx4 float4s) then Wq/Wk/Wv/Wo (65536 float4s each)
// ---------------------------------------------------------------------------
#define NX4 17825792
__global__ __launch_bounds__(256)
void convert_all(const float* __restrict__ x,
                 const float* __restrict__ Wq, const float* __restrict__ Wk,
                 const float* __restrict__ Wv, const float* __restrict__ Wo,
                 __half* __restrict__ xh, __half* __restrict__ wh)
{
    const int i = blockIdx.x * 256 + threadIdx.x;
    const float* src;
    __half2* dst;
    int idx;
    if (i < NX4) {
        src = x; idx = i; dst = (__half2*)xh;
    } else {
        int j = i - NX4;
        int w = j >> 16, jj = j & 65535;
        src = (w == 0) ? Wq : (w == 1) ? Wk : (w == 2) ? Wv : Wo;
        idx = jj;
        dst = (__half2*)(wh + (size_t)w * 262144);
    }
    float4 v = ((const float4*)src)[idx];
    dst[2 * idx]     = __floats2half2_rn(v.x, v.y);
    dst[2 * idx + 1] = __floats2half2_rn(v.z, v.w);
}

// ---------------------------------------------------------------------------
// Attention v7: fp16 q/k/v staging (halved smem: 27.6KB), fp32 scores.
// BUF0h = q then v, BUF1h = k (half stride 72). Padded score writes.
// One CTA per (sample, 4-head group), 128 threads, 4x4 register tiling.
// ---------------------------------------------------------------------------
#define AB0H 0
#define AB1H 4896                // halves (4 heads * 17 rows * 72)
#define ASSF 4896                // floats: scores 4*400
#define ASPF 6496                // floats: P 400
__global__ __launch_bounds__(128)
void attn_kernel(const __half* __restrict__ q, const __half* __restrict__ k,
                 const __half* __restrict__ v, const float* __restrict__ P,
                 __half* __restrict__ ch)
{
    __shared__ float sm[6896];   // 27584 bytes
    __half* smh = (__half*)sm;
    const int n  = blockIdx.x;
    const int hg = blockIdx.y;
    const int t  = threadIdx.x;
    const size_t base = (size_t)n * D_ * M_;
    const uint32_t smb = smem_u32(sm);

    // Phase 1: cp.async stage q -> BUF0h, k -> BUF1h (8 halves per chunk)
    #pragma unroll
    for (int u = 0; u < 5; u++) {
        int f = t + u * 128;
        if (f < 544) {
            int row = f >> 3, c8 = f & 7;        // row = h*17+d (0..67)
            int h = row / 17, d = row % 17;
            size_t goff = base + (size_t)d * 512 + (hg * 4 + h) * 64 + c8 * 8;
            uint32_t soff = (uint32_t)((row * 72 + c8 * 8) * 2);
            cp16(smb + AB0H * 2 + soff, q + goff);
            cp16(smb + AB1H * 2 + soff, k + goff);
        }
    }
    asm volatile("cp.async.commit_group;");
    for (int f = t; f < 289; f += 128)
        sm[ASPF + (f / 17) * 20 + (f % 17)] = P[f];
    asm volatile("cp.async.wait_group 0;");
    __syncthreads();

    // Phase 2: scores (padded 4x4 blocks), fp16 loads -> fp32 math
    if (t < 100) {
        const int h = t / 25, blk = t % 25;
        const int d0 = (blk / 5) * 4, e0 = (blk % 5) * 4;
        const __half* sq = smh + AB0H + (h * 17 + d0) * 72;
        const __half* sk = smh + AB1H + (h * 17 + e0) * 72;
        float acc[4][4];
        #pragma unroll
        for (int i = 0; i < 4; i++)
            #pragma unroll
            for (int j = 0; j < 4; j++) acc[i][j] = 0.f;
        #pragma unroll 8
        for (int c4 = 0; c4 < 16; c4++) {
            float4 qa[4], kb[4];
            #pragma unroll
            for (int i = 0; i < 4; i++) {
                uint2 u = *(const uint2*)(sq + i * 72 + c4 * 4);
                float2 f0 = __half22float2(*(__half2*)&u.x);
                float2 f1 = __half22float2(*(__half2*)&u.y);
                qa[i] = make_float4(f0.x, f0.y, f1.x, f1.y);
            }
            #pragma unroll
            for (int j = 0; j < 4; j++) {
                uint2 u = *(const uint2*)(sk + j * 72 + c4 * 4);
                float2 f0 = __half22float2(*(__half2*)&u.x);
                float2 f1 = __half22float2(*(__half2*)&u.y);
                kb[j] = make_float4(f0.x, f0.y, f1.x, f1.y);
            }
            #pragma unroll
            for (int i = 0; i < 4; i++)
                #pragma unroll
                for (int j = 0; j < 4; j++)
                    acc[i][j] += qa[i].x * kb[j].x + qa[i].y * kb[j].y
                               + qa[i].z * kb[j].z + qa[i].w * kb[j].w;
        }
        float* ss = sm + ASSF + h * 400;
        #pragma unroll
        for (int i = 0; i < 4; i++)
            #pragma unroll
            for (int j = 0; j < 4; j++)
                ss[(d0 + i) * 20 + e0 + j] =
                    acc[i][j] * 0.125f + sm[ASPF + (d0 + i) * 20 + e0 + j];
    }
    __syncthreads();

    // Phase 3: cp.async v into BUF0h (q dead); softmax overlaps.
    #pragma unroll
    for (int u = 0; u < 5; u++) {
        int f = t + u * 128;
        if (f < 544) {
            int row = f >> 3, c8 = f & 7;
            int h = row / 17, d = row % 17;
            size_t goff = base + (size_t)d * 512 + (hg * 4 + h) * 64 + c8 * 8;
            uint32_t soff = (uint32_t)((row * 72 + c8 * 8) * 2);
            cp16(smb + AB0H * 2 + soff, v + goff);
        }
    }
    asm volatile("cp.async.commit_group;");
    if (t < 68) {
        float* row = sm + ASSF + (t / 17) * 400 + (t % 17) * 20;
        float mx = -1e30f;
        #pragma unroll
        for (int e = 0; e < 17; e++) mx = fmaxf(mx, row[e]);
        float sum = 0.f;
        #pragma unroll
        for (int e = 0; e < 17; e++) {
            float ex = __expf(row[e] - mx);
            row[e] = ex;
            sum += ex;
        }
        float inv = 1.f / sum;
        #pragma unroll
        for (int e = 0; e < 17; e++) row[e] *= inv;
    }
    asm volatile("cp.async.wait_group 0;");
    __syncthreads();

    // Phase 4: ctx -> row-major fp16 (contiguous 8B stores)
    for (int task = t; task < 320; task += 128) {
        const int h = task / 80, rem = task % 80;
        const int d0 = (rem / 16) * 4, c0c = (rem % 16) * 4;
        const float* ss = sm + ASSF + h * 400;
        const __half* sv = smh + AB0H + h * 17 * 72 + c0c;
        float acc[4][4];
        #pragma unroll
        for (int i = 0; i < 4; i++)
            #pragma unroll
            for (int j = 0; j < 4; j++) acc[i][j] = 0.f;
        #pragma unroll
        for (int e = 0; e < 17; e++) {
            uint2 u = *(const uint2*)(sv + e * 72);
            float2 f0 = __half22float2(*(__half2*)&u.x);
            float2 f1 = __half22float2(*(__half2*)&u.y);
            #pragma unroll
            for (int i = 0; i < 4; i++) {
                const float w = ss[(d0 + i) * 20 + e];
                acc[i][0] += w * f0.x;
                acc[i][1] += w * f0.y;
                acc[i][2] += w * f1.x;
                acc[i][3] += w * f1.y;
            }
        }
        #pragma unroll
        for (int i = 0; i < 4; i++) {
            const int d = d0 + i;
            if (d < 17) {
                const size_t off = base + (size_t)d * 512 + (hg * 4 + h) * 64 + c0c;
                __half2 h0 = __floats2half2_rn(acc[i][0], acc[i][1]);
                __half2 h1 = __floats2half2_rn(acc[i][2], acc[i][3]);
                uint2 o;
                o.x = *(uint32_t*)&h0;
                o.y = *(uint32_t*)&h1;
                *(uint2*)(ch + off) = o;
            }
        }
    }
}

// ---------------------------------------------------------------------------
// In-place LayerNorm (warp per row, width 512), eps = 1e-5
// ---------------------------------------------------------------------------
__global__ __launch_bounds__(256)
void ln_kernel(float* __restrict__ out, const float* __restrict__ gamma,
               const float* __restrict__ beta)
{
    const int row  = blockIdx.x * 8 + (threadIdx.x >> 5);
    const int lane = threadIdx.x & 31;
    const size_t base = (size_t)row * 512;

    float4 vals[4];
    float sum = 0.f, sq = 0.f;
    #pragma unroll
    for (int j = 0; j < 4; j++) {
        vals[j] = *(const float4*)(out + base + (size_t)(j * 32 + lane) * 4);
        sum += vals[j].x + vals[j].y + vals[j].z + vals[j].w;
        sq  += vals[j].x * vals[j].x + vals[j].y * vals[j].y
             + vals[j].z * vals[j].z + vals[j].w * vals[j].w;
    }
    #pragma unroll
    for (int o = 16; o > 0; o >>= 1) {
        sum += __shfl_xor_sync(0xffffffffu, sum, o);
        sq  += __shfl_xor_sync(0xffffffffu, sq,  o);
    }
    const float mean = sum * (1.f / 512.f);
    const float var  = sq * (1.f / 512.f) - mean * mean;
    const float rstd = rsqrtf(var + 1e-5f);

    #pragma unroll
    for (int j = 0; j < 4; j++) {
        int c = (j * 32 + lane) * 4;
        float4 g  = *(const float4*)(gamma + c);
        float4 bb = *(const float4*)(beta + c);
        float4 v;
        v.x = (vals[j].x - mean) * rstd * g.x + bb.x;
        v.y = (vals[j].y - mean) * rstd * g.y + bb.y;
        v.z = (vals[j].z - mean) * rstd * g.z + bb.z;
        v.w = (vals[j].w - mean) * rstd * g.w + bb.w;
        *(float4*)(out + base + c) = v;
    }
}

// ---------------------------------------------------------------------------
extern "C" void kernel_launch(void* const* d_in, const int* in_sizes, int n_in,
                              void* d_out, int out_size)
{
    const float* x     = (const float*)d_in[0];
    const float* P     = (const float*)d_in[1];
    const float* Wq    = (const float*)d_in[2];
    const float* Wk    = (const float*)d_in[3];
    const float* Wv    = (const float*)d_in[4];
    const float* Wo    = (const float*)d_in[5];
    const float* bo    = (const float*)d_in[6];
    const float* gamma = (const float*)d_in[7];
    const float* beta  = (const float*)d_in[8];
    float* out = (float*)d_out;

    void *pq, *pk, *pv, *pxh, *pch, *pwh;
    cudaGetSymbolAddress(&pq,  g_q);
    cudaGetSymbolAddress(&pk,  g_k);
    cudaGetSymbolAddress(&pv,  g_v);
    cudaGetSymbolAddress(&pxh, g_xh);
    cudaGetSymbolAddress(&pch, g_ch);
    cudaGetSymbolAddress(&pwh, g_wh);

    __half* wh = (__half*)pwh;

    const int dsm = STAGES * STAGE_BYTES;           // 110592
    cudaFuncSetAttribute(gemm_f16<0>, cudaFuncAttributeMaxDynamicSharedMemorySize, dsm);
    cudaFuncSetAttribute(gemm_f16<1>, cudaFuncAttributeMaxDynamicSharedMemorySize, dsm);

    // Merged convert: 18087936 float4s = 70656 blocks
    convert_all<<<70656, 256>>>(x, Wq, Wk, Wv, Wo, (__half*)pxh, wh);

    // Fused QKV projection: 12 col tiles over contiguous [Wq;Wk;Wv] rows
    dim3 gq(12, NROW / 128);
    gemm_f16<0><<<gq, 128, dsm>>>((const __half*)pxh, wh,
                                  pq, pk, pv, nullptr, nullptr);

    dim3 ga(NSAMP, 2);
    attn_kernel<<<ga, 128>>>(
        (const __half*)pq, (const __half*)pk, (const __half*)pv, P, (__half*)pch);

    // fc_out + bias + residual
    dim3 go(4, NROW / 128);
    gemm_f16<1><<<go, 128, dsm>>>((const __half*)pch, wh + 3 * 262144,
                                  out, nullptr, nullptr, bo, x);

    ln_kernel<<<NROW / 8, 256>>>(out, gamma, beta);
}

// round 16
// speedup vs baseline: 2.3210x; 1.0834x over previous
#include <cuda_runtime.h>
#include <cuda_fp16.h>
#include <cstdint>

// Problem constants
#define B_  32
#define S_  256
#define D_  17
#define M_  512
#define H_  8
#define DK_ 64
#define NROW  139264          // B*S*D rows of width 512
#define NSAMP 8192            // B*S

// ---------------------------------------------------------------------------
// Scratch (__device__ globals; allocation-free rule)
// ---------------------------------------------------------------------------
__device__ __half g_q[(size_t)NROW * M_];
__device__ __half g_k[(size_t)NROW * M_];
__device__ __half g_v[(size_t)NROW * M_];
__device__ __half g_xh[(size_t)NROW * M_];      // x in fp16
__device__ __half g_ch[(size_t)NROW * M_];      // ctx in fp16
__device__ __half g_wh[4 * 512 * 512];          // Wq,Wk,Wv,Wo fp16 (contiguous)

// ---------------------------------------------------------------------------
// Helpers
// ---------------------------------------------------------------------------
__device__ __forceinline__ uint32_t smem_u32(const void* p) {
    uint32_t a;
    asm("{ .reg .u64 t; cvta.to.shared.u64 t, %1; cvt.u32.u64 %0, t; }"
        : "=r"(a) : "l"(p));
    return a;
}

__device__ __forceinline__ void cp16(uint32_t dst, const void* src) {
    asm volatile("cp.async.cg.shared.global [%0], [%1], 16;" :: "r"(dst), "l"(src));
}

__device__ __forceinline__ void ldmx4(uint32_t* r, uint32_t addr) {
    asm volatile("ldmatrix.sync.aligned.m8n8.x4.shared.b16 {%0,%1,%2,%3}, [%4];"
                 : "=r"(r[0]), "=r"(r[1]), "=r"(r[2]), "=r"(r[3]) : "r"(addr));
}

__device__ __forceinline__ void mma_f16(float* d, const uint32_t* a,
                                        uint32_t b0, uint32_t b1) {
    asm volatile(
        "mma.sync.aligned.m16n8k16.row.col.f32.f16.f16.f32 "
        "{%0,%1,%2,%3}, {%4,%5,%6,%7}, {%8,%9}, {%0,%1,%2,%3};"
        : "+f"(d[0]), "+f"(d[1]), "+f"(d[2]), "+f"(d[3])
        : "r"(a[0]), "r"(a[1]), "r"(a[2]), "r"(a[3]), "r"(b0), "r"(b1));
}

// ---------------------------------------------------------------------------
// Single-pass fp16 GEMM on HMMA, 2-stage / 3 CTAs-per-SM variant:
// C[r,c] = sum_k A[r,k] * W[c,k],  K=512, BK=64/iter, 8 iters.
// BM=BN=128, 128 threads (4 warps 2x2), warp tile 64x64.
// 2-stage double buffer (73.7KB) + launch_bounds(128,3) -> 12 warps/SM.
// MODE 0: fused q/k/v fp16 output. MODE 1: fp32 out + bias + resid.
// ---------------------------------------------------------------------------
#define ITERS 8
#define ROWB 144
#define STAGE_BYTES (256 * ROWB)
#define STAGES 2

__device__ __forceinline__ void load_iter(
    int tid, uint32_t sbase, int r0, int c0, int it,
    const __half* __restrict__ A, const __half* __restrict__ B)
{
    const int kk = it * 64;
    #pragma unroll
    for (int t = 0; t < 8; t++) {                 // A: 128 rows x 128B
        int f = tid + t * 128;
        int row = f >> 3, ch = f & 7;
        cp16(sbase + row * ROWB + ch * 16, A + ((size_t)(r0 + row) << 9) + kk + ch * 8);
    }
    const uint32_t b0 = sbase + 128 * ROWB;
    #pragma unroll
    for (int t = 0; t < 8; t++) {                 // B: 128 rows x 128B
        int f = tid + t * 128;
        int row = f >> 3, ch = f & 7;
        cp16(b0 + row * ROWB + ch * 16, B + ((size_t)(c0 + row) << 9) + kk + ch * 8);
    }
    asm volatile("cp.async.commit_group;");
}

template<int MODE>
__global__ __launch_bounds__(128, 3)
void gemm_f16(const __half* __restrict__ A, const __half* __restrict__ W,
              void* __restrict__ O0, void* __restrict__ O1, void* __restrict__ O2,
              const float* __restrict__ bias,
              const float* __restrict__ resid)
{
    extern __shared__ __align__(128) char smem[];

    const int tid = threadIdx.x;
    const int wid = tid >> 5;
    const int lid = tid & 31;
    const int c0 = blockIdx.x << 7;    // col tile (fast dim -> A L2 reuse)
    const int r0 = blockIdx.y << 7;
    const int m0 = (wid & 1) * 64;
    const int n0 = (wid >> 1) * 64;
    const uint32_t sb = smem_u32(smem);

    float acc[4][8][4];
    #pragma unroll
    for (int i = 0; i < 4; i++)
        #pragma unroll
        for (int j = 0; j < 8; j++)
            #pragma unroll
            for (int q = 0; q < 4; q++) acc[i][j][q] = 0.f;

    load_iter(tid, sb, r0, c0, 0, A, W);

    const uint32_t a_off = (uint32_t)((m0 + (lid & 15)) * ROWB + ((lid >> 4) << 4));
    const uint32_t b_off = (uint32_t)((n0 + (lid & 7) + ((lid >> 4) << 3)) * ROWB
                                      + (((lid >> 3) & 1) << 4));

    for (int it = 0; it < ITERS; it++) {
        asm volatile("cp.async.wait_group 0;");
        __syncthreads();

        if (it + 1 < ITERS)
            load_iter(tid, sb + ((it + 1) & 1) * STAGE_BYTES, r0, c0, it + 1, A, W);

        const uint32_t as = sb + (it & 1) * STAGE_BYTES;
        const uint32_t bs = as + 128 * ROWB;

        #pragma unroll
        for (int kt = 0; kt < 4; kt++) {
            uint32_t a[4][4], b[4][4];
            #pragma unroll
            for (int mi = 0; mi < 4; mi++)
                ldmx4(a[mi], as + a_off + (uint32_t)(mi * 16 * ROWB + kt * 32));
            #pragma unroll
            for (int nj = 0; nj < 4; nj++)
                ldmx4(b[nj], bs + b_off + (uint32_t)(nj * 16 * ROWB + kt * 32));
            #pragma unroll
            for (int mi = 0; mi < 4; mi++)
                #pragma unroll
                for (int ni = 0; ni < 8; ni++)
                    mma_f16(acc[mi][ni], a[mi],
                            b[ni >> 1][(ni & 1) * 2], b[ni >> 1][(ni & 1) * 2 + 1]);
        }
    }

    // Epilogue
    const int g  = lid >> 2;
    const int tg = lid & 3;
    if (MODE == 0) {
        const int which = c0 >> 9;
        __half* C = (__half*)((which == 0) ? O0 : (which == 1) ? O1 : O2);
        const int col0 = c0 & 511;
        #pragma unroll
        for (int mi = 0; mi < 4; mi++) {
            #pragma unroll
            for (int ni = 0; ni < 8; ni++) {
                const int r = r0 + m0 + mi * 16 + g;
                const int c = col0 + n0 + ni * 8 + tg * 2;
                *(__half2*)(C + ((size_t)r << 9) + c) =
                    __floats2half2_rn(acc[mi][ni][0], acc[mi][ni][1]);
                *(__half2*)(C + ((size_t)(r + 8) << 9) + c) =
                    __floats2half2_rn(acc[mi][ni][2], acc[mi][ni][3]);
            }
        }
    } else {
        float* C = (float*)O0;
        #pragma unroll
        for (int mi = 0; mi < 4; mi++) {
            #pragma unroll
            for (int ni = 0; ni < 8; ni++) {
                const int r = r0 + m0 + mi * 16 + g;
                const int c = c0 + n0 + ni * 8 + tg * 2;
                float2 v0 = make_float2(acc[mi][ni][0], acc[mi][ni][1]);
                float2 v1 = make_float2(acc[mi][ni][2], acc[mi][ni][3]);
                const float2 bb = *(const float2*)(bias + c);
                const float2 q0 = *(const float2*)(resid + ((size_t)r << 9) + c);
                const float2 q1 = *(const float2*)(resid + ((size_t)(r + 8) << 9) + c);
                v0.x += bb.x + q0.x; v0.y += bb.y + q0.y;
                v1.x += bb.x + q1.x; v1.y += bb.y + q1.y;
                *(float2*)(C + ((size_t)r << 9) + c)       = v0;
                *(float2*)(C + ((size_t)(r + 8) << 9) + c) = v1;
            }
        }
    }
}

// ---------------------------------------------------------------------------
// Merged convert: x (NX4 float4s) then Wq/Wk/Wv/Wo (65536 float4s each)
// ---------------------------------------------------------------------------
#define NX4 17825792
__global__ __launch_bounds__(256)
void convert_all(const float* __restrict__ x,
                 const float* __restrict__ Wq, const float* __restrict__ Wk,
                 const float* __restrict__ Wv, const float* __restrict__ Wo,
                 __half* __restrict__ xh, __half* __restrict__ wh)
{
    const int i = blockIdx.x * 256 + threadIdx.x;
    const float* src;
    __half2* dst;
    int idx;
    if (i < NX4) {
        src = x; idx = i; dst = (__half2*)xh;
    } else {
        int j = i - NX4;
        int w = j >> 16, jj = j & 65535;
        src = (w == 0) ? Wq : (w == 1) ? Wk : (w == 2) ? Wv : Wo;
        idx = jj;
        dst = (__half2*)(wh + (size_t)w * 262144);
    }
    float4 v = ((const float4*)src)[idx];
    dst[2 * idx]     = __floats2half2_rn(v.x, v.y);
    dst[2 * idx + 1] = __floats2half2_rn(v.z, v.w);
}

// ---------------------------------------------------------------------------
// Attention v7 (R15, unchanged): fp16 q/k/v staging, fp32 scores.
// BUF0h = q then v, BUF1h = k (half stride 72). Padded score writes.
// ---------------------------------------------------------------------------
#define AB0H 0
#define AB1H 4896                // halves (4 heads * 17 rows * 72)
#define ASSF 4896                // floats: scores 4*400
#define ASPF 6496                // floats: P 400
__global__ __launch_bounds__(128)
void attn_kernel(const __half* __restrict__ q, const __half* __restrict__ k,
                 const __half* __restrict__ v, const float* __restrict__ P,
                 __half* __restrict__ ch)
{
    __shared__ float sm[6896];   // 27584 bytes
    __half* smh = (__half*)sm;
    const int n  = blockIdx.x;
    const int hg = blockIdx.y;
    const int t  = threadIdx.x;
    const size_t base = (size_t)n * D_ * M_;
    const uint32_t smb = smem_u32(sm);

    // Phase 1: cp.async stage q -> BUF0h, k -> BUF1h
    #pragma unroll
    for (int u = 0; u < 5; u++) {
        int f = t + u * 128;
        if (f < 544) {
            int row = f >> 3, c8 = f & 7;        // row = h*17+d (0..67)
            int h = row / 17, d = row % 17;
            size_t goff = base + (size_t)d * 512 + (hg * 4 + h) * 64 + c8 * 8;
            uint32_t soff = (uint32_t)((row * 72 + c8 * 8) * 2);
            cp16(smb + AB0H * 2 + soff, q + goff);
            cp16(smb + AB1H * 2 + soff, k + goff);
        }
    }
    asm volatile("cp.async.commit_group;");
    for (int f = t; f < 289; f += 128)
        sm[ASPF + (f / 17) * 20 + (f % 17)] = P[f];
    asm volatile("cp.async.wait_group 0;");
    __syncthreads();

    // Phase 2: scores (padded 4x4 blocks), fp16 loads -> fp32 math
    if (t < 100) {
        const int h = t / 25, blk = t % 25;
        const int d0 = (blk / 5) * 4, e0 = (blk % 5) * 4;
        const __half* sq = smh + AB0H + (h * 17 + d0) * 72;
        const __half* sk = smh + AB1H + (h * 17 + e0) * 72;
        float acc[4][4];
        #pragma unroll
        for (int i = 0; i < 4; i++)
            #pragma unroll
            for (int j = 0; j < 4; j++) acc[i][j] = 0.f;
        #pragma unroll 8
        for (int c4 = 0; c4 < 16; c4++) {
            float4 qa[4], kb[4];
            #pragma unroll
            for (int i = 0; i < 4; i++) {
                uint2 u = *(const uint2*)(sq + i * 72 + c4 * 4);
                float2 f0 = __half22float2(*(__half2*)&u.x);
                float2 f1 = __half22float2(*(__half2*)&u.y);
                qa[i] = make_float4(f0.x, f0.y, f1.x, f1.y);
            }
            #pragma unroll
            for (int j = 0; j < 4; j++) {
                uint2 u = *(const uint2*)(sk + j * 72 + c4 * 4);
                float2 f0 = __half22float2(*(__half2*)&u.x);
                float2 f1 = __half22float2(*(__half2*)&u.y);
                kb[j] = make_float4(f0.x, f0.y, f1.x, f1.y);
            }
            #pragma unroll
            for (int i = 0; i < 4; i++)
                #pragma unroll
                for (int j = 0; j < 4; j++)
                    acc[i][j] += qa[i].x * kb[j].x + qa[i].y * kb[j].y
                               + qa[i].z * kb[j].z + qa[i].w * kb[j].w;
        }
        float* ss = sm + ASSF + h * 400;
        #pragma unroll
        for (int i = 0; i < 4; i++)
            #pragma unroll
            for (int j = 0; j < 4; j++)
                ss[(d0 + i) * 20 + e0 + j] =
                    acc[i][j] * 0.125f + sm[ASPF + (d0 + i) * 20 + e0 + j];
    }
    __syncthreads();

    // Phase 3: cp.async v into BUF0h (q dead); softmax overlaps.
    #pragma unroll
    for (int u = 0; u < 5; u++) {
        int f = t + u * 128;
        if (f < 544) {
            int row = f >> 3, c8 = f & 7;
            int h = row / 17, d = row % 17;
            size_t goff = base + (size_t)d * 512 + (hg * 4 + h) * 64 + c8 * 8;
            uint32_t soff = (uint32_t)((row * 72 + c8 * 8) * 2);
            cp16(smb + AB0H * 2 + soff, v + goff);
        }
    }
    asm volatile("cp.async.commit_group;");
    if (t < 68) {
        float* row = sm + ASSF + (t / 17) * 400 + (t % 17) * 20;
        float mx = -1e30f;
        #pragma unroll
        for (int e = 0; e < 17; e++) mx = fmaxf(mx, row[e]);
        float sum = 0.f;
        #pragma unroll
        for (int e = 0; e < 17; e++) {
            float ex = __expf(row[e] - mx);
            row[e] = ex;
            sum += ex;
        }
        float inv = 1.f / sum;
        #pragma unroll
        for (int e = 0; e < 17; e++) row[e] *= inv;
    }
    asm volatile("cp.async.wait_group 0;");
    __syncthreads();

    // Phase 4: ctx -> row-major fp16 (contiguous 8B stores)
    for (int task = t; task < 320; task += 128) {
        const int h = task / 80, rem = task % 80;
        const int d0 = (rem / 16) * 4, c0c = (rem % 16) * 4;
        const float* ss = sm + ASSF + h * 400;
        const __half* sv = smh + AB0H + h * 17 * 72 + c0c;
        float acc[4][4];
        #pragma unroll
        for (int i = 0; i < 4; i++)
            #pragma unroll
            for (int j = 0; j < 4; j++) acc[i][j] = 0.f;
        #pragma unroll
        for (int e = 0; e < 17; e++) {
            uint2 u = *(const uint2*)(sv + e * 72);
            float2 f0 = __half22float2(*(__half2*)&u.x);
            float2 f1 = __half22float2(*(__half2*)&u.y);
            #pragma unroll
            for (int i = 0; i < 4; i++) {
                const float w = ss[(d0 + i) * 20 + e];
                acc[i][0] += w * f0.x;
                acc[i][1] += w * f0.y;
                acc[i][2] += w * f1.x;
                acc[i][3] += w * f1.y;
            }
        }
        #pragma unroll
        for (int i = 0; i < 4; i++) {
            const int d = d0 + i;
            if (d < 17) {
                const size_t off = base + (size_t)d * 512 + (hg * 4 + h) * 64 + c0c;
                __half2 h0 = __floats2half2_rn(acc[i][0], acc[i][1]);
                __half2 h1 = __floats2half2_rn(acc[i][2], acc[i][3]);
                uint2 o;
                o.x = *(uint32_t*)&h0;
                o.y = *(uint32_t*)&h1;
                *(uint2*)(ch + off) = o;
            }
        }
    }
}

// ---------------------------------------------------------------------------
// In-place LayerNorm (warp per row, width 512), eps = 1e-5
// ---------------------------------------------------------------------------
__global__ __launch_bounds__(256)
void ln_kernel(float* __restrict__ out, const float* __restrict__ gamma,
               const float* __restrict__ beta)
{
    const int row  = blockIdx.x * 8 + (threadIdx.x >> 5);
    const int lane = threadIdx.x & 31;
    const size_t base = (size_t)row * 512;

    float4 vals[4];
    float sum = 0.f, sq = 0.f;
    #pragma unroll
    for (int j = 0; j < 4; j++) {
        vals[j] = *(const float4*)(out + base + (size_t)(j * 32 + lane) * 4);
        sum += vals[j].x + vals[j].y + vals[j].z + vals[j].w;
        sq  += vals[j].x * vals[j].x + vals[j].y * vals[j].y
             + vals[j].z * vals[j].z + vals[j].w * vals[j].w;
    }
    #pragma unroll
    for (int o = 16; o > 0; o >>= 1) {
        sum += __shfl_xor_sync(0xffffffffu, sum, o);
        sq  += __shfl_xor_sync(0xffffffffu, sq,  o);
    }
    const float mean = sum * (1.f / 512.f);
    const float var  = sq * (1.f / 512.f) - mean * mean;
    const float rstd = rsqrtf(var + 1e-5f);

    #pragma unroll
    for (int j = 0; j < 4; j++) {
        int c = (j * 32 + lane) * 4;
        float4 g  = *(const float4*)(gamma + c);
        float4 bb = *(const float4*)(beta + c);
        float4 v;
        v.x = (vals[j].x - mean) * rstd * g.x + bb.x;
        v.y = (vals[j].y - mean) * rstd * g.y + bb.y;
        v.z = (vals[j].z - mean) * rstd * g.z + bb.z;
        v.w = (vals[j].w - mean) * rstd * g.w + bb.w;
        *(float4*)(out + base + c) = v;
    }
}

// ---------------------------------------------------------------------------
extern "C" void kernel_launch(void* const* d_in, const int* in_sizes, int n_in,
                              void* d_out, int out_size)
{
    const float* x     = (const float*)d_in[0];
    const float* P     = (const float*)d_in[1];
    const float* Wq    = (const float*)d_in[2];
    const float* Wk    = (const float*)d_in[3];
    const float* Wv    = (const float*)d_in[4];
    const float* Wo    = (const float*)d_in[5];
    const float* bo    = (const float*)d_in[6];
    const float* gamma = (const float*)d_in[7];
    const float* beta  = (const float*)d_in[8];
    float* out = (float*)d_out;

    void *pq, *pk, *pv, *pxh, *pch, *pwh;
    cudaGetSymbolAddress(&pq,  g_q);
    cudaGetSymbolAddress(&pk,  g_k);
    cudaGetSymbolAddress(&pv,  g_v);
    cudaGetSymbolAddress(&pxh, g_xh);
    cudaGetSymbolAddress(&pch, g_ch);
    cudaGetSymbolAddress(&pwh, g_wh);

    __half* wh = (__half*)pwh;

    const int dsm = STAGES * STAGE_BYTES;           // 73728
    cudaFuncSetAttribute(gemm_f16<0>, cudaFuncAttributeMaxDynamicSharedMemorySize, dsm);
    cudaFuncSetAttribute(gemm_f16<1>, cudaFuncAttributeMaxDynamicSharedMemorySize, dsm);

    // Merged convert: 18087936 float4s = 70656 blocks
    convert_all<<<70656, 256>>>(x, Wq, Wk, Wv, Wo, (__half*)pxh, wh);

    // Fused QKV projection: 12 col tiles over contiguous [Wq;Wk;Wv] rows
    dim3 gq(12, NROW / 128);
    gemm_f16<0><<<gq, 128, dsm>>>((const __half*)pxh, wh,
                                  pq, pk, pv, nullptr, nullptr);

    dim3 ga(NSAMP, 2);
    attn_kernel<<<ga, 128>>>(
        (const __half*)pq, (const __half*)pk, (const __half*)pv, P, (__half*)pch);

    // fc_out + bias + residual
    dim3 go(4, NROW / 128);
    gemm_f16<1><<<go, 128, dsm>>>((const __half*)pch, wh + 3 * 262144,
                                  out, nullptr, nullptr, bo, x);

    ln_kernel<<<NROW / 8, 256>>>(out, gamma, beta);
}